// round 13
// baseline (speedup 1.0000x reference)
#include <cuda_runtime.h>
#include <cuda_bf16.h>
#include <math.h>
#include <stdint.h>

// ---------------------------------------------------------------------------
// Problem constants
// ---------------------------------------------------------------------------
#define NN    50000
#define EE    800000
#define EMB   256
#define HID   512
#define DDISC 64
#define DCONT 13
#define CAT   (4*EMB)      // 1024
#define SLOPE 0.01f

// transposed-weight pool offsets ([N,K] row-major, bf16)
#define OW_DG  0            // combined [512,64]: rows 0-255 Wd, 256-511 Wg0
#define OW_G1  32768        // [256,256]
#define OW_G2  98304        // [256,256]
#define OW_F   163840       // [512,1024]
#define OW_L1  688128       // [256,512]
#define OW_TOT 819200

// ---------------------------------------------------------------------------
// Scratch — __device__ globals (no cudaMalloc allowed)
// ---------------------------------------------------------------------------
__device__ float g_Y [(long)NN*EMB];     // conv pre-aggregation (fp32)
__device__ float g_S [(long)NN*EMB];     // s
__device__ float g_Hp[(long)NN*HID];     // partial fusion accumulator (fp32)
__device__ float g_sci[NN];
__device__ float g_dinv[NN];
__device__ float g_b2[2*EMB];            // concat(bd, bg0)
__device__ int   g_cnt[NN];
__device__ int   g_rowptr[NN+1];
__device__ int   g_cursor[NN];
__device__ int   g_colsrc[EE];
__device__ int   g_blksum[64];
__device__ int   g_blkoff[64];
__device__ int   g_is64;

// bf16 split buffers (hi/lo)
__device__ __align__(16) __nv_bfloat16 g_Ah[(long)NN*CAT];   // concat split
__device__ __align__(16) __nv_bfloat16 g_Al[(long)NN*CAT];
__device__ __align__(16) __nv_bfloat16 g_Gh[(long)NN*EMB];   // gcn activation split
__device__ __align__(16) __nv_bfloat16 g_Gl[(long)NN*EMB];
__device__ __align__(16) __nv_bfloat16 g_Hh[(long)NN*HID];   // h_ci split
__device__ __align__(16) __nv_bfloat16 g_Hl[(long)NN*HID];
__device__ __align__(16) __nv_bfloat16 g_Dh[(long)NN*DDISC]; // discrete_x split
__device__ __align__(16) __nv_bfloat16 g_Dl[(long)NN*DDISC];
__device__ __align__(16) __nv_bfloat16 g_Wth[OW_TOT];        // transposed weight pool
__device__ __align__(16) __nv_bfloat16 g_Wtl[OW_TOT];

// ---------------------------------------------------------------------------
// asm helpers (base ISA only — must compile for compute_103)
// ---------------------------------------------------------------------------
__device__ __forceinline__ uint32_t smem_u32(const void* p) {
    uint32_t a;
    asm("{ .reg .u64 t; cvta.to.shared.u64 t, %1; cvt.u32.u64 %0, t; }" : "=r"(a) : "l"(p));
    return a;
}
__device__ __forceinline__ void ldsm4(uint32_t& r0, uint32_t& r1, uint32_t& r2, uint32_t& r3,
                                      uint32_t addr) {
    asm volatile("ldmatrix.sync.aligned.m8n8.x4.shared.b16 {%0,%1,%2,%3}, [%4];"
                 : "=r"(r0), "=r"(r1), "=r"(r2), "=r"(r3) : "r"(addr));
}
__device__ __forceinline__ void mma16816(float* c, const uint32_t* a, const uint32_t* b) {
    asm volatile(
        "mma.sync.aligned.m16n8k16.row.col.f32.bf16.bf16.f32 "
        "{%0,%1,%2,%3}, {%4,%5,%6,%7}, {%8,%9}, {%0,%1,%2,%3};"
        : "+f"(c[0]), "+f"(c[1]), "+f"(c[2]), "+f"(c[3])
        : "r"(a[0]), "r"(a[1]), "r"(a[2]), "r"(a[3]), "r"(b[0]), "r"(b[1]));
}
__device__ __forceinline__ void cp16(uint32_t dst, const void* src, int sz) {
    asm volatile("cp.async.cg.shared.global [%0], [%1], 16, %2;"
                 :: "r"(dst), "l"(src), "r"(sz) : "memory");
}
__device__ __forceinline__ void cp_commit() {
    asm volatile("cp.async.commit_group;" ::: "memory");
}
__device__ __forceinline__ void cp_wait1() {
    asm volatile("cp.async.wait_group 1;" ::: "memory");
}
__device__ __forceinline__ void cp_wait0() {
    asm volatile("cp.async.wait_group 0;" ::: "memory");
}
// byte offset inside a [rows][32 halfs] tile (row stride 64B, 16B-chunk swizzle)
__device__ __forceinline__ uint32_t swa(int r, int ci) {
    return (uint32_t)(r * 64 + ((ci ^ (r & 3) ^ ((r >> 2) & 1)) * 16));
}
__device__ __forceinline__ void split_store(__nv_bfloat16* H, __nv_bfloat16* L,
                                            size_t off, float v0, float v1) {
    __nv_bfloat16 h0 = __float2bfloat16(v0);
    __nv_bfloat16 h1 = __float2bfloat16(v1);
    __nv_bfloat16 l0 = __float2bfloat16(v0 - __bfloat162float(h0));
    __nv_bfloat16 l1 = __float2bfloat16(v1 - __bfloat162float(h1));
    *(__nv_bfloat162*)(H + off) = __nv_bfloat162(h0, h1);
    *(__nv_bfloat162*)(L + off) = __nv_bfloat162(l0, l1);
}

// ---------------------------------------------------------------------------
// bf16x3 HMMA GEMM, cp.async double-buffered, warp tile 64x64 (4 warps).
// CTA tile 128x128, 128 threads, K-chunk 32, K%32==0, N%128==0.
// A stride sA, B stride sB (element strides; allow K-slices of wider mats).
// MODE 0: write Cf fp32.
// MODE 3: dual split dest — cols < 256 -> (Ch,Cl,lds); cols >= 256 -> (Ch2,Cl2,lds2).
// MODE 4: v = acc + Part[gr*ldf+gc] + bias -> act -> Cf, Cf2 (fp32) + split (Ch,Cl).
// Dynamic smem: 2 stages x 32KB = 64KB.
// ---------------------------------------------------------------------------
#define STG 32768
template<int ACT, int MODE>
__global__ __launch_bounds__(128, 2)
void mma_gemm_kernel(const __nv_bfloat16* __restrict__ Ah,
                     const __nv_bfloat16* __restrict__ Al,
                     const __nv_bfloat16* __restrict__ Bh,   // [N, sB]
                     const __nv_bfloat16* __restrict__ Bl,
                     const float* __restrict__ bias,
                     const float* __restrict__ Part,
                     float* __restrict__ Cf, float* __restrict__ Cf2, int ldf,
                     __nv_bfloat16* __restrict__ Ch, __nv_bfloat16* __restrict__ Cl, int lds,
                     __nv_bfloat16* __restrict__ Ch2, __nv_bfloat16* __restrict__ Cl2, int lds2,
                     int M, int K, int sA, int sB, int N)
{
    extern __shared__ char sm[];
    const uint32_t sb = smem_u32(sm);
    const uint32_t oAH = 0, oAL = 8192, oBH = 16384, oBL = 24576;

    int tid = threadIdx.x;
    int wid = tid >> 5;
    int lane = tid & 31;
    int wm = wid & 1;              // 2 warp-rows of 64
    int wn = wid >> 1;             // 2 warp-cols of 64
    int row0 = blockIdx.y * 128;
    int col0 = blockIdx.x * 128;

    float acc[4][8][4];
    #pragma unroll
    for (int i = 0; i < 4; i++)
        #pragma unroll
        for (int j = 0; j < 8; j++)
            #pragma unroll
            for (int q = 0; q < 4; q++) acc[i][j][q] = 0.f;

    int Lg = lane >> 3;
    int Lr = lane & 7;
    const int nchunks = K >> 5;

    auto prefetch = [&](int ch, int stage) {
        int k0 = ch << 5;
        uint32_t base = sb + stage * STG;
        #pragma unroll
        for (int it = 0; it < 4; it++) {
            int idx = tid + it * 128;          // 0..511
            int r = idx >> 2, ci = idx & 3;
            uint32_t sw = swa(r, ci);
            int gr = row0 + r;
            int ok = (gr < M) ? 16 : 0;
            size_t ga = (size_t)(ok ? gr : 0) * sA + k0 + ci * 8;
            cp16(base + oAH + sw, Ah + ga, ok);
            cp16(base + oAL + sw, Al + ga, ok);
            size_t gb = (size_t)(col0 + r) * sB + k0 + ci * 8;
            cp16(base + oBH + sw, Bh + gb, 16);
            cp16(base + oBL + sw, Bl + gb, 16);
        }
        cp_commit();
    };

    prefetch(0, 0);
    for (int ch = 0; ch < nchunks; ch++) {
        if (ch + 1 < nchunks) {
            prefetch(ch + 1, (ch + 1) & 1);
            cp_wait1();
        } else {
            cp_wait0();
        }
        __syncthreads();
        uint32_t base = sb + (ch & 1) * STG;

        #pragma unroll
        for (int ks = 0; ks < 2; ks++) {
            uint32_t ah[4][4], al[4][4];
            #pragma unroll
            for (int ma = 0; ma < 4; ma++) {
                int ar = wm * 64 + ma * 16 + Lr + (Lg & 1) * 8;
                int ac = ks * 2 + (Lg >> 1);
                uint32_t sw = swa(ar, ac);
                ldsm4(ah[ma][0], ah[ma][1], ah[ma][2], ah[ma][3], base + oAH + sw);
                ldsm4(al[ma][0], al[ma][1], al[ma][2], al[ma][3], base + oAL + sw);
            }
            #pragma unroll
            for (int g = 0; g < 4; g++) {
                int br = wn * 64 + g * 16 + Lr + (Lg >> 1) * 8;
                int bc = ks * 2 + (Lg & 1);
                uint32_t sw = swa(br, bc);
                uint32_t bh[4], bl[4];
                ldsm4(bh[0], bh[1], bh[2], bh[3], base + oBH + sw);
                ldsm4(bl[0], bl[1], bl[2], bl[3], base + oBL + sw);
                #pragma unroll
                for (int ma = 0; ma < 4; ma++) {
                    mma16816(acc[ma][g*2+0], ah[ma], bh + 0);
                    mma16816(acc[ma][g*2+1], ah[ma], bh + 2);
                    mma16816(acc[ma][g*2+0], ah[ma], bl + 0);
                    mma16816(acc[ma][g*2+1], ah[ma], bl + 2);
                    mma16816(acc[ma][g*2+0], al[ma], bh + 0);
                    mma16816(acc[ma][g*2+1], al[ma], bh + 2);
                }
            }
        }
        __syncthreads();
    }

    // ---- epilogue ----
    int rbase = row0 + wm * 64 + (lane >> 2);
    int cbase = col0 + wn * 64 + (lane & 3) * 2;
    #pragma unroll
    for (int ma = 0; ma < 4; ma++) {
        #pragma unroll
        for (int na = 0; na < 8; na++) {
            int gc = cbase + na * 8;
            float b0 = bias ? bias[gc] : 0.f;
            float b1 = bias ? bias[gc + 1] : 0.f;
            #pragma unroll
            for (int h = 0; h < 2; h++) {
                int gr = rbase + ma * 16 + h * 8;
                if (gr < M) {
                    float v0 = acc[ma][na][h * 2 + 0] + b0;
                    float v1 = acc[ma][na][h * 2 + 1] + b1;
                    if (MODE == 4) {
                        float2 p = *(const float2*)(Part + (size_t)gr * ldf + gc);
                        v0 += p.x;
                        v1 += p.y;
                    }
                    if (ACT == 1) {
                        v0 = v0 > 0.f ? v0 : SLOPE * v0;
                        v1 = v1 > 0.f ? v1 : SLOPE * v1;
                    }
                    if (MODE == 0) {
                        *(float2*)(Cf + (size_t)gr * ldf + gc) = make_float2(v0, v1);
                    }
                    if (MODE == 4) {
                        *(float2*)(Cf + (size_t)gr * ldf + gc) = make_float2(v0, v1);
                        *(float2*)(Cf2 + (size_t)gr * ldf + gc) = make_float2(v0, v1);
                        split_store(Ch, Cl, (size_t)gr * lds + gc, v0, v1);
                    }
                    if (MODE == 3) {
                        if (gc < 256)
                            split_store(Ch, Cl, (size_t)gr * lds + gc, v0, v1);
                        else
                            split_store(Ch2, Cl2, (size_t)gr * lds2 + (gc - 256), v0, v1);
                    }
                }
            }
        }
    }
}

// ---------------------------------------------------------------------------
// input feature split (fp32 -> bf16 hi/lo)
// ---------------------------------------------------------------------------
__global__ void splitA_kernel(const float* __restrict__ X,
                              __nv_bfloat16* __restrict__ H,
                              __nv_bfloat16* __restrict__ L, long n)
{
    long i = (long)blockIdx.x * blockDim.x + threadIdx.x;
    if (i >= n) return;
    float a = X[i];
    __nv_bfloat16 h = __float2bfloat16(a);
    H[i] = h;
    L[i] = __float2bfloat16(a - __bfloat162float(h));
}

// ---------------------------------------------------------------------------
// ONE kernel: transpose+split ALL weights into the pool, plus bias concat.
// ---------------------------------------------------------------------------
__global__ void splitW_all_kernel(const float* __restrict__ Wd,  const float* __restrict__ Wg0,
                                  const float* __restrict__ Wg1, const float* __restrict__ Wg2,
                                  const float* __restrict__ Wf,  const float* __restrict__ Wl1,
                                  const float* __restrict__ bd,  const float* __restrict__ bg0)
{
    const int c0 = DDISC*EMB;            // 16384
    const int c1 = c0 + DDISC*EMB;       // 32768
    const int c2 = c1 + EMB*EMB;         // 98304
    const int c3 = c2 + EMB*EMB;         // 163840
    const int c4 = c3 + CAT*HID;         // 688128
    const int c5 = c4 + HID*EMB;         // 819200
    for (long i = (long)blockIdx.x * blockDim.x + threadIdx.x;
         i < c5 + 2*EMB; i += (long)gridDim.x * blockDim.x) {
        if (i >= c5) {                   // bias concat tail
            int j = (int)(i - c5);
            g_b2[j] = (j < EMB) ? bd[j] : bg0[j - EMB];
            continue;
        }
        const float* W; long loc, off; int K, N;
        if (i < c0)      { W = Wd;  loc = i;      off = OW_DG;           K = DDISC; N = EMB; }
        else if (i < c1) { W = Wg0; loc = i - c0; off = OW_DG + (long)EMB*DDISC; K = DDISC; N = EMB; }
        else if (i < c2) { W = Wg1; loc = i - c1; off = OW_G1; K = EMB; N = EMB; }
        else if (i < c3) { W = Wg2; loc = i - c2; off = OW_G2; K = EMB; N = EMB; }
        else if (i < c4) { W = Wf;  loc = i - c3; off = OW_F;  K = CAT; N = HID; }
        else             { W = Wl1; loc = i - c4; off = OW_L1; K = HID; N = EMB; }
        int k = (int)(loc / N), nn = (int)(loc % N);
        float a = W[loc];
        __nv_bfloat16 h = __float2bfloat16(a);
        long o = off + (long)nn * K + k;
        g_Wth[o] = h;
        g_Wtl[o] = __float2bfloat16(a - __bfloat162float(h));
    }
}

// ---------------------------------------------------------------------------
// Edge dtype probe + graph preprocessing
// ---------------------------------------------------------------------------
__global__ void probe_kernel(const int* __restrict__ ei32, int nwords)
{
    __shared__ int nz;
    if (threadIdx.x == 0) nz = 0;
    __syncthreads();
    int lim = nwords < 4096 ? nwords : 4096;
    for (int i = 1 + 2 * threadIdx.x; i < lim; i += 2 * blockDim.x)
        if (ei32[i] != 0) atomicAdd(&nz, 1);
    __syncthreads();
    if (threadIdx.x == 0) g_is64 = (nz == 0) ? 1 : 0;
}

__device__ __forceinline__ int edge_at(const void* base, long i, int is64)
{
    return is64 ? (int)((const long long*)base)[i] : ((const int*)base)[i];
}

__global__ void zero_cnt_kernel(int n) {
    int i = blockIdx.x * blockDim.x + threadIdx.x;
    if (i < n) g_cnt[i] = 0;
}

__global__ void count_kernel(const void* __restrict__ ei, int e, int n) {
    int i = blockIdx.x * blockDim.x + threadIdx.x;
    if (i >= e) return;
    int is64 = g_is64;
    int d = edge_at(ei, (long)e + i, is64);
    if ((unsigned)d < (unsigned)n) atomicAdd(&g_cnt[d], 1);
}

// ---- 3-phase multi-block scan ----
__global__ __launch_bounds__(1024)
void scan1_kernel(int n) {
    __shared__ int sh[1024];
    int i = blockIdx.x * 1024 + threadIdx.x;
    int v = (i < n) ? g_cnt[i] : 0;
    if (i < n) g_dinv[i] = rsqrtf((float)(v + 1));
    sh[threadIdx.x] = v;
    __syncthreads();
    #pragma unroll
    for (int off = 512; off > 0; off >>= 1) {
        if (threadIdx.x < off) sh[threadIdx.x] += sh[threadIdx.x + off];
        __syncthreads();
    }
    if (threadIdx.x == 0) g_blksum[blockIdx.x] = sh[0];
}

__global__ void scan2_kernel(int nblk) {
    __shared__ int sh[64];
    int t = threadIdx.x;
    int v = (t < nblk) ? g_blksum[t] : 0;
    sh[t] = v;
    __syncthreads();
    #pragma unroll
    for (int off = 1; off < 64; off <<= 1) {
        int u = (t >= off) ? sh[t - off] : 0;
        __syncthreads();
        sh[t] += u;
        __syncthreads();
    }
    if (t < nblk) g_blkoff[t] = sh[t] - v;
}

__global__ __launch_bounds__(1024)
void scan3_kernel(int n, int nblk) {
    __shared__ int sh[1024];
    int i = blockIdx.x * 1024 + threadIdx.x;
    int v = (i < n) ? g_cnt[i] : 0;
    sh[threadIdx.x] = v;
    __syncthreads();
    #pragma unroll
    for (int off = 1; off < 1024; off <<= 1) {
        int u = (threadIdx.x >= off) ? sh[threadIdx.x - off] : 0;
        __syncthreads();
        sh[threadIdx.x] += u;
        __syncthreads();
    }
    int off0 = g_blkoff[blockIdx.x];
    if (i < n) {
        int ex = off0 + sh[threadIdx.x] - v;
        g_rowptr[i] = ex;
        g_cursor[i] = ex;
    }
    if (blockIdx.x == nblk - 1 && threadIdx.x == 1023)
        g_rowptr[n] = off0 + sh[1023];
}

__global__ void fill_kernel(const void* __restrict__ ei, int e, int n) {
    int i = blockIdx.x * blockDim.x + threadIdx.x;
    if (i >= e) return;
    int is64 = g_is64;
    int s = edge_at(ei, i, is64);
    int d = edge_at(ei, (long)e + i, is64);
    if ((unsigned)d < (unsigned)n && (unsigned)s < (unsigned)n) {
        int pos = atomicAdd(&g_cursor[d], 1);
        if (pos < EE) g_colsrc[pos] = s;
    }
}

// ---------------------------------------------------------------------------
// Merged continuous embeds (K=13), one launch: half = blockIdx.x>>1.
// ---------------------------------------------------------------------------
__global__ __launch_bounds__(256)
void cont_embed_kernel(const float* __restrict__ X,   // continous_x [M, 39]
                       const float* __restrict__ Wc1, const float* __restrict__ bc1,
                       const float* __restrict__ Wc2, const float* __restrict__ bc2,
                       __nv_bfloat16* __restrict__ Ch, __nv_bfloat16* __restrict__ Cl,
                       int M)
{
    const int K = DCONT, NC = EMB, lda = 3*DCONT;
    int half = blockIdx.x >> 1;
    int col0 = (blockIdx.x & 1) * 128;
    const float* A = X + half * DCONT;
    const float* W = half ? Wc2 : Wc1;
    const float* bias = half ? bc2 : bc1;
    __nv_bfloat16* OH = Ch + (1 + half) * EMB;
    __nv_bfloat16* OL = Cl + (1 + half) * EMB;

    __shared__ float As[16][128];
    __shared__ float Ws[16][128];

    int tid = threadIdx.x;
    int tx = tid & 15;
    int ty = tid >> 4;
    int row0 = blockIdx.y * 128;

    float acc[8][8];
    #pragma unroll
    for (int i = 0; i < 8; i++)
        #pragma unroll
        for (int j = 0; j < 8; j++) acc[i][j] = 0.f;

    {
        int a_row = tid >> 1;
        int a_col = (tid & 1) * 8;
        #pragma unroll
        for (int j = 0; j < 8; j++) {
            int r = row0 + a_row, c = a_col + j;
            As[a_col + j][a_row] = (r < M && c < K) ? A[(long)r * lda + c] : 0.f;
        }
        int w_k = tid >> 5;
        int w_n = (tid & 31) * 4;
        #pragma unroll
        for (int rep = 0; rep < 2; rep++) {
            int kk = w_k + rep * 8;
            #pragma unroll
            for (int j = 0; j < 4; j++) {
                int nn = col0 + w_n + j;
                Ws[kk][w_n + j] = (kk < K) ? W[(long)kk * NC + nn] : 0.f;
            }
        }
    }
    __syncthreads();
    #pragma unroll
    for (int k = 0; k < 13; k++) {
        float a[8], b[8];
        #pragma unroll
        for (int i = 0; i < 8; i++) a[i] = As[k][ty * 8 + i];
        #pragma unroll
        for (int j = 0; j < 8; j++) b[j] = Ws[k][tx * 8 + j];
        #pragma unroll
        for (int i = 0; i < 8; i++)
            #pragma unroll
            for (int j = 0; j < 8; j++)
                acc[i][j] += a[i] * b[j];
    }

    #pragma unroll
    for (int i = 0; i < 8; i++) {
        int r = row0 + ty * 8 + i;
        if (r >= M) continue;
        #pragma unroll
        for (int j = 0; j < 8; j += 2) {
            int c = col0 + tx * 8 + j;
            float v0 = acc[i][j] + bias[c];
            float v1 = acc[i][j + 1] + bias[c + 1];
            v0 = v0 > 0.f ? v0 : SLOPE * v0;
            v1 = v1 > 0.f ? v1 : SLOPE * v1;
            split_store(OH, OL, (size_t)r * CAT + c, v0, v1);
        }
    }
}

// ---------------------------------------------------------------------------
// GCN aggregation (one warp per node), float4 gathers, writes bf16 split.
// ---------------------------------------------------------------------------
__global__ __launch_bounds__(256)
void agg_kernel(const float* __restrict__ Y, const float* __restrict__ bias,
                __nv_bfloat16* __restrict__ Oh, __nv_bfloat16* __restrict__ Ol,
                int ldc, int n)
{
    int warp = (blockIdx.x * blockDim.x + threadIdx.x) >> 5;
    int lane = threadIdx.x & 31;
    if (warp >= n) return;
    int beg = g_rowptr[warp], end = g_rowptr[warp + 1];
    int c0 = lane * 8;
    float4 a0 = make_float4(0.f, 0.f, 0.f, 0.f);
    float4 a1 = make_float4(0.f, 0.f, 0.f, 0.f);
    for (int e = beg; e < end; e++) {
        int s = g_colsrc[e];
        float w = g_dinv[s];
        const float4* yr = (const float4*)(Y + (size_t)s * EMB + c0);
        float4 y0 = yr[0], y1 = yr[1];
        a0.x += y0.x * w; a0.y += y0.y * w; a0.z += y0.z * w; a0.w += y0.w * w;
        a1.x += y1.x * w; a1.y += y1.y * w; a1.z += y1.z * w; a1.w += y1.w * w;
    }
    float di = g_dinv[warp];
    float dii = di * di;
    const float4* ys = (const float4*)(Y + (size_t)warp * EMB + c0);
    float4 s0 = ys[0], s1 = ys[1];
    const float4* bp = (const float4*)(bias + c0);
    float4 b0 = bp[0], b1 = bp[1];
    float v[8];
    v[0] = di * a0.x + dii * s0.x + b0.x;
    v[1] = di * a0.y + dii * s0.y + b0.y;
    v[2] = di * a0.z + dii * s0.z + b0.z;
    v[3] = di * a0.w + dii * s0.w + b0.w;
    v[4] = di * a1.x + dii * s1.x + b1.x;
    v[5] = di * a1.y + dii * s1.y + b1.y;
    v[6] = di * a1.z + dii * s1.z + b1.z;
    v[7] = di * a1.w + dii * s1.w + b1.w;
    size_t ob = (size_t)warp * ldc + c0;
    #pragma unroll
    for (int j = 0; j < 8; j += 2) {
        float v0 = v[j] > 0.f ? v[j] : SLOPE * v[j];
        float v1 = v[j+1] > 0.f ? v[j+1] : SLOPE * v[j+1];
        split_store(Oh, Ol, ob + j, v0, v1);
    }
}

// ---------------------------------------------------------------------------
// Final sigmoid head + small s_ci writeout
// ---------------------------------------------------------------------------
__global__ __launch_bounds__(256)
void final_kernel(const float* __restrict__ Wl2, const float* __restrict__ bl2, int n)
{
    int warp = (blockIdx.x * blockDim.x + threadIdx.x) >> 5;
    int lane = threadIdx.x & 31;
    if (warp >= n) return;
    const float* sr = g_S + (long)warp * EMB;
    float a = 0.f;
    #pragma unroll
    for (int j = 0; j < 8; j++) {
        int c = lane + 32 * j;
        a += sr[c] * Wl2[c];
    }
    #pragma unroll
    for (int off = 16; off > 0; off >>= 1)
        a += __shfl_xor_sync(0xffffffffu, a, off);
    if (lane == 0)
        g_sci[warp] = 1.f / (1.f + expf(-(a + bl2[0])));
}

__global__ void sci_writeout_kernel(float* __restrict__ out, int n)
{
    int i = blockIdx.x * blockDim.x + threadIdx.x;
    if (i < n) {
        float v = g_sci[i];
        out[i] = v;
        out[n + i] = v;
        out[2L * n + i] = v;
    }
}

// ---------------------------------------------------------------------------
// Launch: fork-join stream overlap + split fusion GEMM.
// Side stream: CSR prep, cont embeds, then PARTIAL fusion (K=0..768) while
// the main stream runs the GCN chain. Final fusion (K=768..1024) adds the
// partial accumulator.
// ---------------------------------------------------------------------------
extern "C" void kernel_launch(void* const* d_in, const int* in_sizes, int n_in,
                              void* d_out, int out_size)
{
    const float* discrete_x = (const float*)d_in[0];
    const float* continous_x = (const float*)d_in[1];
    const float* Wd  = (const float*)d_in[2];
    const float* bd  = (const float*)d_in[3];
    const float* Wc1 = (const float*)d_in[4];
    const float* bc1 = (const float*)d_in[5];
    const float* Wc2 = (const float*)d_in[6];
    const float* bc2 = (const float*)d_in[7];
    const float* Wg0 = (const float*)d_in[8];
    const float* bg0 = (const float*)d_in[9];
    const float* Wg1 = (const float*)d_in[10];
    const float* bg1 = (const float*)d_in[11];
    const float* Wg2 = (const float*)d_in[12];
    const float* bg2 = (const float*)d_in[13];
    const float* Wf  = (const float*)d_in[14];
    const float* bf  = (const float*)d_in[15];
    const float* Wl1 = (const float*)d_in[16];
    const float* bl1 = (const float*)d_in[17];
    const float* Wl2 = (const float*)d_in[18];
    const float* bl2 = (const float*)d_in[19];
    const void*  edge_index = d_in[20];

    const int n = in_sizes[0] / DDISC;       // 50000
    const int e = in_sizes[20] / 2;          // 800000
    const int nblk = (n + 1023) / 1024;      // 49

    float *pY, *pS, *pB2, *pHp;
    cudaGetSymbolAddress((void**)&pY, g_Y);
    cudaGetSymbolAddress((void**)&pS, g_S);
    cudaGetSymbolAddress((void**)&pB2, g_b2);
    cudaGetSymbolAddress((void**)&pHp, g_Hp);
    __nv_bfloat16 *pAh, *pAl, *pGh, *pGl, *pHh, *pHl, *pDh, *pDl, *pWth, *pWtl;
    cudaGetSymbolAddress((void**)&pAh, g_Ah);
    cudaGetSymbolAddress((void**)&pAl, g_Al);
    cudaGetSymbolAddress((void**)&pGh, g_Gh);
    cudaGetSymbolAddress((void**)&pGl, g_Gl);
    cudaGetSymbolAddress((void**)&pHh, g_Hh);
    cudaGetSymbolAddress((void**)&pHl, g_Hl);
    cudaGetSymbolAddress((void**)&pDh, g_Dh);
    cudaGetSymbolAddress((void**)&pDl, g_Dl);
    cudaGetSymbolAddress((void**)&pWth, g_Wth);
    cudaGetSymbolAddress((void**)&pWtl, g_Wtl);

    cudaFuncSetAttribute(mma_gemm_kernel<0,0>, cudaFuncAttributeMaxDynamicSharedMemorySize, 2*STG);
    cudaFuncSetAttribute(mma_gemm_kernel<1,0>, cudaFuncAttributeMaxDynamicSharedMemorySize, 2*STG);
    cudaFuncSetAttribute(mma_gemm_kernel<1,3>, cudaFuncAttributeMaxDynamicSharedMemorySize, 2*STG);
    cudaFuncSetAttribute(mma_gemm_kernel<1,4>, cudaFuncAttributeMaxDynamicSharedMemorySize, 2*STG);

    dim3 blk(256);
    dim3 gblk(128);
    const int mtiles = (n + 127) / 128;   // 391
    float* outf = (float*)d_out;
    long tot = (long)n * HID;
    __nv_bfloat16* nb = nullptr;
    float* nf = nullptr;

    // ---- fork: side stream ----
    cudaStream_t s1;
    cudaStreamCreateWithFlags(&s1, cudaStreamNonBlocking);
    cudaEvent_t eFork, eDisc, eCSR, ePart;
    cudaEventCreateWithFlags(&eFork, cudaEventDisableTiming);
    cudaEventCreateWithFlags(&eDisc, cudaEventDisableTiming);
    cudaEventCreateWithFlags(&eCSR,  cudaEventDisableTiming);
    cudaEventCreateWithFlags(&ePart, cudaEventDisableTiming);
    cudaEventRecord(eFork, 0);
    cudaStreamWaitEvent(s1, eFork, 0);

    // side stream: edge CSR build + dinv
    probe_kernel<<<1, 256, 0, s1>>>((const int*)edge_index, 2 * e);
    zero_cnt_kernel<<<(n + 255) / 256, blk, 0, s1>>>(n);
    count_kernel<<<(e + 255) / 256, blk, 0, s1>>>(edge_index, e, n);
    scan1_kernel<<<nblk, 1024, 0, s1>>>(n);
    scan2_kernel<<<1, 64, 0, s1>>>(nblk);
    scan3_kernel<<<nblk, 1024, 0, s1>>>(n, nblk);
    fill_kernel<<<(e + 255) / 256, blk, 0, s1>>>(edge_index, e, n);
    cudaEventRecord(eCSR, s1);
    // continuous embeds into concat cols [256, 768)
    cont_embed_kernel<<<dim3(4, mtiles), blk, 0, s1>>>(continous_x, Wc1, bc1, Wc2, bc2,
                                                       pAh, pAl, n);

    // main stream: weight/feature splits + discrete GEMM
    splitW_all_kernel<<<592, blk>>>(Wd, Wg0, Wg1, Wg2, Wf, Wl1, bd, bg0);
    {
        long nd = (long)n * DDISC;
        splitA_kernel<<<(unsigned)((nd + 255) / 256), blk>>>(discrete_x, pDh, pDl, nd);
    }
    mma_gemm_kernel<1,3><<<dim3(4, mtiles), gblk, 2*STG>>>(
        pDh, pDl, pWth + OW_DG, pWtl + OW_DG, pB2, nf,
        nf, nf, 0, pAh, pAl, CAT, pGh, pGl, EMB, n, DDISC, DDISC, DDISC, 512);
    cudaEventRecord(eDisc, 0);

    // side stream: partial fusion Hp = X4[:, :768] @ Wf[:768, :]
    cudaStreamWaitEvent(s1, eDisc, 0);
    mma_gemm_kernel<0,0><<<dim3(4, mtiles), gblk, 2*STG, s1>>>(
        pAh, pAl, pWth + OW_F, pWtl + OW_F, nf, nf,
        pHp, nf, HID, nb, nb, 0, nb, nb, 0, n, 768, CAT, CAT, HID);
    cudaEventRecord(ePart, s1);

    // main: GCN conv 1
    mma_gemm_kernel<0,0><<<dim3(2, mtiles), gblk, 2*STG>>>(
        pGh, pGl, pWth + OW_G1, pWtl + OW_G1, nf, nf,
        pY, nf, EMB, nb, nb, 0, nb, nb, 0, n, EMB, EMB, EMB, EMB);
    cudaStreamWaitEvent(0, eCSR, 0);   // agg1 needs CSR
    agg_kernel<<<(n * 32 + 255) / 256, blk>>>(pY, bg1, pGh, pGl, EMB, n);

    // main: GCN conv 2
    mma_gemm_kernel<0,0><<<dim3(2, mtiles), gblk, 2*STG>>>(
        pGh, pGl, pWth + OW_G2, pWtl + OW_G2, nf, nf,
        pY, nf, EMB, nb, nb, 0, nb, nb, 0, n, EMB, EMB, EMB, EMB);
    agg_kernel<<<(n * 32 + 255) / 256, blk>>>(pY, bg2, pAh + 3*EMB, pAl + 3*EMB, CAT, n);

    // main: final fusion (K=256 tail) + partial accumulator
    cudaStreamWaitEvent(0, ePart, 0);
    mma_gemm_kernel<1,4><<<dim3(4, mtiles), gblk, 2*STG>>>(
        pAh + 3*EMB, pAl + 3*EMB, pWth + OW_F + 3*EMB, pWtl + OW_F + 3*EMB, bf, pHp,
        outf + 3L * n, outf + 3L * n + tot, HID, pHh, pHl, HID, nb, nb, 0,
        n, 256, CAT, CAT, HID);

    // main: Wl1 GEMM
    mma_gemm_kernel<1,0><<<dim3(2, mtiles), gblk, 2*STG>>>(
        pHh, pHl, pWth + OW_L1, pWtl + OW_L1, bl1, nf,
        pS, nf, EMB, nb, nb, 0, nb, nb, 0, n, HID, HID, HID, EMB);

    // ---- final sigmoid head + s_ci writeout ----
    final_kernel<<<(n * 32 + 255) / 256, blk>>>(Wl2, bl2, n);
    sci_writeout_kernel<<<(n + 255) / 256, blk>>>(outf, n);

    // NOTE: s1/events intentionally not destroyed — destroying objects that
    // participated in an ongoing capture invalidates it. Host-side only.
}

// round 14
// speedup vs baseline: 1.1119x; 1.1119x over previous
#include <cuda_runtime.h>
#include <cuda_bf16.h>
#include <math.h>
#include <stdint.h>

// ---------------------------------------------------------------------------
// Problem constants
// ---------------------------------------------------------------------------
#define NN    50000
#define EE    800000
#define EMB   256
#define HID   512
#define DDISC 64
#define DCONT 13
#define CAT   (4*EMB)      // 1024
#define SLOPE 0.01f

// transposed-weight pool offsets ([N,K] row-major, bf16)
#define OW_DG  0            // combined [512,64]: rows 0-255 Wd, 256-511 Wg0
#define OW_G1  32768        // [256,256]
#define OW_G2  98304        // [256,256]
#define OW_F   163840       // [512,1024]
#define OW_L1  688128       // [256,512]
#define OW_TOT 819200

// ---------------------------------------------------------------------------
// Scratch — __device__ globals (no cudaMalloc allowed)
// ---------------------------------------------------------------------------
__device__ float g_Y [(long)NN*EMB];     // conv pre-aggregation (fp32)
__device__ float g_dot[NN];              // fused head dot accumulator
__device__ float g_sci[NN];
__device__ float g_dinv[NN];
__device__ float g_b2[2*EMB];            // concat(bd, bg0)
__device__ int   g_cnt[NN];
__device__ int   g_rowptr[NN+1];
__device__ int   g_cursor[NN];
__device__ int   g_colsrc[EE];
__device__ int   g_blksum[64];
__device__ int   g_blkoff[64];
__device__ int   g_is64;

// bf16 split buffers (hi/lo)
__device__ __align__(16) __nv_bfloat16 g_Ah[(long)NN*CAT];   // concat split
__device__ __align__(16) __nv_bfloat16 g_Al[(long)NN*CAT];
__device__ __align__(16) __nv_bfloat16 g_Gh[(long)NN*EMB];   // gcn activation split
__device__ __align__(16) __nv_bfloat16 g_Gl[(long)NN*EMB];
__device__ __align__(16) __nv_bfloat16 g_Hh[(long)NN*HID];   // h_ci split
__device__ __align__(16) __nv_bfloat16 g_Hl[(long)NN*HID];
__device__ __align__(16) __nv_bfloat16 g_Dh[(long)NN*DDISC]; // discrete_x split
__device__ __align__(16) __nv_bfloat16 g_Dl[(long)NN*DDISC];
__device__ __align__(16) __nv_bfloat16 g_Wth[OW_TOT];        // transposed weight pool
__device__ __align__(16) __nv_bfloat16 g_Wtl[OW_TOT];

// ---------------------------------------------------------------------------
// asm helpers (base ISA only — must compile for compute_103)
// ---------------------------------------------------------------------------
__device__ __forceinline__ uint32_t smem_u32(const void* p) {
    uint32_t a;
    asm("{ .reg .u64 t; cvta.to.shared.u64 t, %1; cvt.u32.u64 %0, t; }" : "=r"(a) : "l"(p));
    return a;
}
__device__ __forceinline__ void ldsm4(uint32_t& r0, uint32_t& r1, uint32_t& r2, uint32_t& r3,
                                      uint32_t addr) {
    asm volatile("ldmatrix.sync.aligned.m8n8.x4.shared.b16 {%0,%1,%2,%3}, [%4];"
                 : "=r"(r0), "=r"(r1), "=r"(r2), "=r"(r3) : "r"(addr));
}
__device__ __forceinline__ void mma16816(float* c, const uint32_t* a, const uint32_t* b) {
    asm volatile(
        "mma.sync.aligned.m16n8k16.row.col.f32.bf16.bf16.f32 "
        "{%0,%1,%2,%3}, {%4,%5,%6,%7}, {%8,%9}, {%0,%1,%2,%3};"
        : "+f"(c[0]), "+f"(c[1]), "+f"(c[2]), "+f"(c[3])
        : "r"(a[0]), "r"(a[1]), "r"(a[2]), "r"(a[3]), "r"(b[0]), "r"(b[1]));
}
__device__ __forceinline__ void cp16(uint32_t dst, const void* src, int sz) {
    asm volatile("cp.async.cg.shared.global [%0], [%1], 16, %2;"
                 :: "r"(dst), "l"(src), "r"(sz) : "memory");
}
__device__ __forceinline__ void cp_commit() {
    asm volatile("cp.async.commit_group;" ::: "memory");
}
__device__ __forceinline__ void cp_wait1() {
    asm volatile("cp.async.wait_group 1;" ::: "memory");
}
__device__ __forceinline__ void cp_wait0() {
    asm volatile("cp.async.wait_group 0;" ::: "memory");
}
// byte offset inside a [rows][32 halfs] tile (row stride 64B, 16B-chunk swizzle)
__device__ __forceinline__ uint32_t swa(int r, int ci) {
    return (uint32_t)(r * 64 + ((ci ^ (r & 3) ^ ((r >> 2) & 1)) * 16));
}
__device__ __forceinline__ void split_store(__nv_bfloat16* H, __nv_bfloat16* L,
                                            size_t off, float v0, float v1) {
    __nv_bfloat16 h0 = __float2bfloat16(v0);
    __nv_bfloat16 h1 = __float2bfloat16(v1);
    __nv_bfloat16 l0 = __float2bfloat16(v0 - __bfloat162float(h0));
    __nv_bfloat16 l1 = __float2bfloat16(v1 - __bfloat162float(h1));
    *(__nv_bfloat162*)(H + off) = __nv_bfloat162(h0, h1);
    *(__nv_bfloat162*)(L + off) = __nv_bfloat162(l0, l1);
}

// ---------------------------------------------------------------------------
// bf16x3 HMMA GEMM, cp.async double-buffered, warp tile 64x64 (4 warps).
// CTA tile 128x128, 128 threads, K-chunk 32, K%32==0, N%128==0.
// A stride sA, B stride sB (element strides).
// MODE 0: write Cf fp32.
// MODE 2: write split (Ch,Cl) + fp32 into Cf AND Cf2.
// MODE 3: dual split dest — cols < 256 -> (Ch,Cl,lds); cols >= 256 -> (Ch2,Cl2,lds2).
// MODE 5: fused head — v = act(acc+bias); atomicAdd(Cf[row], sum(v * Wv[col])).
//         Wv passed via Part. No matrix stores.
// Dynamic smem: 2 stages x 32KB = 64KB.
// ---------------------------------------------------------------------------
#define STG 32768
template<int ACT, int MODE>
__global__ __launch_bounds__(128, 2)
void mma_gemm_kernel(const __nv_bfloat16* __restrict__ Ah,
                     const __nv_bfloat16* __restrict__ Al,
                     const __nv_bfloat16* __restrict__ Bh,   // [N, sB]
                     const __nv_bfloat16* __restrict__ Bl,
                     const float* __restrict__ bias,
                     const float* __restrict__ Part,
                     float* __restrict__ Cf, float* __restrict__ Cf2, int ldf,
                     __nv_bfloat16* __restrict__ Ch, __nv_bfloat16* __restrict__ Cl, int lds,
                     __nv_bfloat16* __restrict__ Ch2, __nv_bfloat16* __restrict__ Cl2, int lds2,
                     int M, int K, int sA, int sB, int N)
{
    extern __shared__ char sm[];
    const uint32_t sb = smem_u32(sm);
    const uint32_t oAH = 0, oAL = 8192, oBH = 16384, oBL = 24576;

    int tid = threadIdx.x;
    int wid = tid >> 5;
    int lane = tid & 31;
    int wm = wid & 1;              // 2 warp-rows of 64
    int wn = wid >> 1;             // 2 warp-cols of 64
    int row0 = blockIdx.y * 128;
    int col0 = blockIdx.x * 128;

    float acc[4][8][4];
    #pragma unroll
    for (int i = 0; i < 4; i++)
        #pragma unroll
        for (int j = 0; j < 8; j++)
            #pragma unroll
            for (int q = 0; q < 4; q++) acc[i][j][q] = 0.f;

    int Lg = lane >> 3;
    int Lr = lane & 7;
    const int nchunks = K >> 5;

    auto prefetch = [&](int ch, int stage) {
        int k0 = ch << 5;
        uint32_t base = sb + stage * STG;
        #pragma unroll
        for (int it = 0; it < 4; it++) {
            int idx = tid + it * 128;          // 0..511
            int r = idx >> 2, ci = idx & 3;
            uint32_t sw = swa(r, ci);
            int gr = row0 + r;
            int ok = (gr < M) ? 16 : 0;
            size_t ga = (size_t)(ok ? gr : 0) * sA + k0 + ci * 8;
            cp16(base + oAH + sw, Ah + ga, ok);
            cp16(base + oAL + sw, Al + ga, ok);
            size_t gb = (size_t)(col0 + r) * sB + k0 + ci * 8;
            cp16(base + oBH + sw, Bh + gb, 16);
            cp16(base + oBL + sw, Bl + gb, 16);
        }
        cp_commit();
    };

    prefetch(0, 0);
    for (int ch = 0; ch < nchunks; ch++) {
        if (ch + 1 < nchunks) {
            prefetch(ch + 1, (ch + 1) & 1);
            cp_wait1();
        } else {
            cp_wait0();
        }
        __syncthreads();
        uint32_t base = sb + (ch & 1) * STG;

        #pragma unroll
        for (int ks = 0; ks < 2; ks++) {
            uint32_t ah[4][4], al[4][4];
            #pragma unroll
            for (int ma = 0; ma < 4; ma++) {
                int ar = wm * 64 + ma * 16 + Lr + (Lg & 1) * 8;
                int ac = ks * 2 + (Lg >> 1);
                uint32_t sw = swa(ar, ac);
                ldsm4(ah[ma][0], ah[ma][1], ah[ma][2], ah[ma][3], base + oAH + sw);
                ldsm4(al[ma][0], al[ma][1], al[ma][2], al[ma][3], base + oAL + sw);
            }
            #pragma unroll
            for (int g = 0; g < 4; g++) {
                int br = wn * 64 + g * 16 + Lr + (Lg >> 1) * 8;
                int bc = ks * 2 + (Lg & 1);
                uint32_t sw = swa(br, bc);
                uint32_t bh[4], bl[4];
                ldsm4(bh[0], bh[1], bh[2], bh[3], base + oBH + sw);
                ldsm4(bl[0], bl[1], bl[2], bl[3], base + oBL + sw);
                #pragma unroll
                for (int ma = 0; ma < 4; ma++) {
                    mma16816(acc[ma][g*2+0], ah[ma], bh + 0);
                    mma16816(acc[ma][g*2+1], ah[ma], bh + 2);
                    mma16816(acc[ma][g*2+0], ah[ma], bl + 0);
                    mma16816(acc[ma][g*2+1], ah[ma], bl + 2);
                    mma16816(acc[ma][g*2+0], al[ma], bh + 0);
                    mma16816(acc[ma][g*2+1], al[ma], bh + 2);
                }
            }
        }
        __syncthreads();
    }

    // ---- epilogue ----
    int rbase = row0 + wm * 64 + (lane >> 2);
    int cbase = col0 + wn * 64 + (lane & 3) * 2;

    if (MODE == 5) {
        // fused head: dot(act(acc+bias), Part) per row -> atomicAdd
        #pragma unroll
        for (int ma = 0; ma < 4; ma++) {
            #pragma unroll
            for (int h = 0; h < 2; h++) {
                int gr = rbase + ma * 16 + h * 8;
                float d = 0.f;
                #pragma unroll
                for (int na = 0; na < 8; na++) {
                    int gc = cbase + na * 8;
                    float v0 = acc[ma][na][h * 2 + 0] + bias[gc];
                    float v1 = acc[ma][na][h * 2 + 1] + bias[gc + 1];
                    v0 = v0 > 0.f ? v0 : SLOPE * v0;
                    v1 = v1 > 0.f ? v1 : SLOPE * v1;
                    d += v0 * Part[gc] + v1 * Part[gc + 1];
                }
                d += __shfl_xor_sync(0xffffffffu, d, 1);
                d += __shfl_xor_sync(0xffffffffu, d, 2);
                if ((lane & 3) == 0 && gr < M) atomicAdd(Cf + gr, d);
            }
        }
        return;
    }

    #pragma unroll
    for (int ma = 0; ma < 4; ma++) {
        #pragma unroll
        for (int na = 0; na < 8; na++) {
            int gc = cbase + na * 8;
            float b0 = bias ? bias[gc] : 0.f;
            float b1 = bias ? bias[gc + 1] : 0.f;
            #pragma unroll
            for (int h = 0; h < 2; h++) {
                int gr = rbase + ma * 16 + h * 8;
                if (gr < M) {
                    float v0 = acc[ma][na][h * 2 + 0] + b0;
                    float v1 = acc[ma][na][h * 2 + 1] + b1;
                    if (ACT == 1) {
                        v0 = v0 > 0.f ? v0 : SLOPE * v0;
                        v1 = v1 > 0.f ? v1 : SLOPE * v1;
                    }
                    if (MODE == 0 || MODE == 2) {
                        *(float2*)(Cf + (size_t)gr * ldf + gc) = make_float2(v0, v1);
                        if (MODE == 2)
                            *(float2*)(Cf2 + (size_t)gr * ldf + gc) = make_float2(v0, v1);
                    }
                    if (MODE == 2)
                        split_store(Ch, Cl, (size_t)gr * lds + gc, v0, v1);
                    if (MODE == 3) {
                        if (gc < 256)
                            split_store(Ch, Cl, (size_t)gr * lds + gc, v0, v1);
                        else
                            split_store(Ch2, Cl2, (size_t)gr * lds2 + (gc - 256), v0, v1);
                    }
                }
            }
        }
    }
}

// ---------------------------------------------------------------------------
// input feature split (fp32 -> bf16 hi/lo)
// ---------------------------------------------------------------------------
__global__ void splitA_kernel(const float* __restrict__ X,
                              __nv_bfloat16* __restrict__ H,
                              __nv_bfloat16* __restrict__ L, long n)
{
    long i = (long)blockIdx.x * blockDim.x + threadIdx.x;
    if (i >= n) return;
    float a = X[i];
    __nv_bfloat16 h = __float2bfloat16(a);
    H[i] = h;
    L[i] = __float2bfloat16(a - __bfloat162float(h));
}

// ---------------------------------------------------------------------------
// ONE kernel: transpose+split ALL weights into the pool, plus bias concat.
// ---------------------------------------------------------------------------
__global__ void splitW_all_kernel(const float* __restrict__ Wd,  const float* __restrict__ Wg0,
                                  const float* __restrict__ Wg1, const float* __restrict__ Wg2,
                                  const float* __restrict__ Wf,  const float* __restrict__ Wl1,
                                  const float* __restrict__ bd,  const float* __restrict__ bg0)
{
    const int c0 = DDISC*EMB;            // 16384
    const int c1 = c0 + DDISC*EMB;       // 32768
    const int c2 = c1 + EMB*EMB;         // 98304
    const int c3 = c2 + EMB*EMB;         // 163840
    const int c4 = c3 + CAT*HID;         // 688128
    const int c5 = c4 + HID*EMB;         // 819200
    for (long i = (long)blockIdx.x * blockDim.x + threadIdx.x;
         i < c5 + 2*EMB; i += (long)gridDim.x * blockDim.x) {
        if (i >= c5) {                   // bias concat tail
            int j = (int)(i - c5);
            g_b2[j] = (j < EMB) ? bd[j] : bg0[j - EMB];
            continue;
        }
        const float* W; long loc, off; int K, N;
        if (i < c0)      { W = Wd;  loc = i;      off = OW_DG;           K = DDISC; N = EMB; }
        else if (i < c1) { W = Wg0; loc = i - c0; off = OW_DG + (long)EMB*DDISC; K = DDISC; N = EMB; }
        else if (i < c2) { W = Wg1; loc = i - c1; off = OW_G1; K = EMB; N = EMB; }
        else if (i < c3) { W = Wg2; loc = i - c2; off = OW_G2; K = EMB; N = EMB; }
        else if (i < c4) { W = Wf;  loc = i - c3; off = OW_F;  K = CAT; N = HID; }
        else             { W = Wl1; loc = i - c4; off = OW_L1; K = HID; N = EMB; }
        int k = (int)(loc / N), nn = (int)(loc % N);
        float a = W[loc];
        __nv_bfloat16 h = __float2bfloat16(a);
        long o = off + (long)nn * K + k;
        g_Wth[o] = h;
        g_Wtl[o] = __float2bfloat16(a - __bfloat162float(h));
    }
}

// ---------------------------------------------------------------------------
// Edge dtype probe + graph preprocessing
// ---------------------------------------------------------------------------
__global__ void probe_kernel(const int* __restrict__ ei32, int nwords)
{
    __shared__ int nz;
    if (threadIdx.x == 0) nz = 0;
    __syncthreads();
    int lim = nwords < 4096 ? nwords : 4096;
    for (int i = 1 + 2 * threadIdx.x; i < lim; i += 2 * blockDim.x)
        if (ei32[i] != 0) atomicAdd(&nz, 1);
    __syncthreads();
    if (threadIdx.x == 0) g_is64 = (nz == 0) ? 1 : 0;
}

__device__ __forceinline__ int edge_at(const void* base, long i, int is64)
{
    return is64 ? (int)((const long long*)base)[i] : ((const int*)base)[i];
}

__global__ void zero_cnt_kernel(int n) {
    int i = blockIdx.x * blockDim.x + threadIdx.x;
    if (i < n) {
        g_cnt[i] = 0;
        g_dot[i] = 0.f;
    }
}

__global__ void count_kernel(const void* __restrict__ ei, int e, int n) {
    int i = blockIdx.x * blockDim.x + threadIdx.x;
    if (i >= e) return;
    int is64 = g_is64;
    int d = edge_at(ei, (long)e + i, is64);
    if ((unsigned)d < (unsigned)n) atomicAdd(&g_cnt[d], 1);
}

// ---- 3-phase multi-block scan ----
__global__ __launch_bounds__(1024)
void scan1_kernel(int n) {
    __shared__ int sh[1024];
    int i = blockIdx.x * 1024 + threadIdx.x;
    int v = (i < n) ? g_cnt[i] : 0;
    if (i < n) g_dinv[i] = rsqrtf((float)(v + 1));
    sh[threadIdx.x] = v;
    __syncthreads();
    #pragma unroll
    for (int off = 512; off > 0; off >>= 1) {
        if (threadIdx.x < off) sh[threadIdx.x] += sh[threadIdx.x + off];
        __syncthreads();
    }
    if (threadIdx.x == 0) g_blksum[blockIdx.x] = sh[0];
}

__global__ void scan2_kernel(int nblk) {
    __shared__ int sh[64];
    int t = threadIdx.x;
    int v = (t < nblk) ? g_blksum[t] : 0;
    sh[t] = v;
    __syncthreads();
    #pragma unroll
    for (int off = 1; off < 64; off <<= 1) {
        int u = (t >= off) ? sh[t - off] : 0;
        __syncthreads();
        sh[t] += u;
        __syncthreads();
    }
    if (t < nblk) g_blkoff[t] = sh[t] - v;
}

__global__ __launch_bounds__(1024)
void scan3_kernel(int n, int nblk) {
    __shared__ int sh[1024];
    int i = blockIdx.x * 1024 + threadIdx.x;
    int v = (i < n) ? g_cnt[i] : 0;
    sh[threadIdx.x] = v;
    __syncthreads();
    #pragma unroll
    for (int off = 1; off < 1024; off <<= 1) {
        int u = (threadIdx.x >= off) ? sh[threadIdx.x - off] : 0;
        __syncthreads();
        sh[threadIdx.x] += u;
        __syncthreads();
    }
    int off0 = g_blkoff[blockIdx.x];
    if (i < n) {
        int ex = off0 + sh[threadIdx.x] - v;
        g_rowptr[i] = ex;
        g_cursor[i] = ex;
    }
    if (blockIdx.x == nblk - 1 && threadIdx.x == 1023)
        g_rowptr[n] = off0 + sh[1023];
}

__global__ void fill_kernel(const void* __restrict__ ei, int e, int n) {
    int i = blockIdx.x * blockDim.x + threadIdx.x;
    if (i >= e) return;
    int is64 = g_is64;
    int s = edge_at(ei, i, is64);
    int d = edge_at(ei, (long)e + i, is64);
    if ((unsigned)d < (unsigned)n && (unsigned)s < (unsigned)n) {
        int pos = atomicAdd(&g_cursor[d], 1);
        if (pos < EE) g_colsrc[pos] = s;
    }
}

// ---------------------------------------------------------------------------
// Merged continuous embeds (K=13), one launch: half = blockIdx.x>>1.
// ---------------------------------------------------------------------------
__global__ __launch_bounds__(256)
void cont_embed_kernel(const float* __restrict__ X,   // continous_x [M, 39]
                       const float* __restrict__ Wc1, const float* __restrict__ bc1,
                       const float* __restrict__ Wc2, const float* __restrict__ bc2,
                       __nv_bfloat16* __restrict__ Ch, __nv_bfloat16* __restrict__ Cl,
                       int M)
{
    const int K = DCONT, NC = EMB, lda = 3*DCONT;
    int half = blockIdx.x >> 1;
    int col0 = (blockIdx.x & 1) * 128;
    const float* A = X + half * DCONT;
    const float* W = half ? Wc2 : Wc1;
    const float* bias = half ? bc2 : bc1;
    __nv_bfloat16* OH = Ch + (1 + half) * EMB;
    __nv_bfloat16* OL = Cl + (1 + half) * EMB;

    __shared__ float As[16][128];
    __shared__ float Ws[16][128];

    int tid = threadIdx.x;
    int tx = tid & 15;
    int ty = tid >> 4;
    int row0 = blockIdx.y * 128;

    float acc[8][8];
    #pragma unroll
    for (int i = 0; i < 8; i++)
        #pragma unroll
        for (int j = 0; j < 8; j++) acc[i][j] = 0.f;

    {
        int a_row = tid >> 1;
        int a_col = (tid & 1) * 8;
        #pragma unroll
        for (int j = 0; j < 8; j++) {
            int r = row0 + a_row, c = a_col + j;
            As[a_col + j][a_row] = (r < M && c < K) ? A[(long)r * lda + c] : 0.f;
        }
        int w_k = tid >> 5;
        int w_n = (tid & 31) * 4;
        #pragma unroll
        for (int rep = 0; rep < 2; rep++) {
            int kk = w_k + rep * 8;
            #pragma unroll
            for (int j = 0; j < 4; j++) {
                int nn = col0 + w_n + j;
                Ws[kk][w_n + j] = (kk < K) ? W[(long)kk * NC + nn] : 0.f;
            }
        }
    }
    __syncthreads();
    #pragma unroll
    for (int k = 0; k < 13; k++) {
        float a[8], b[8];
        #pragma unroll
        for (int i = 0; i < 8; i++) a[i] = As[k][ty * 8 + i];
        #pragma unroll
        for (int j = 0; j < 8; j++) b[j] = Ws[k][tx * 8 + j];
        #pragma unroll
        for (int i = 0; i < 8; i++)
            #pragma unroll
            for (int j = 0; j < 8; j++)
                acc[i][j] += a[i] * b[j];
    }

    #pragma unroll
    for (int i = 0; i < 8; i++) {
        int r = row0 + ty * 8 + i;
        if (r >= M) continue;
        #pragma unroll
        for (int j = 0; j < 8; j += 2) {
            int c = col0 + tx * 8 + j;
            float v0 = acc[i][j] + bias[c];
            float v1 = acc[i][j + 1] + bias[c + 1];
            v0 = v0 > 0.f ? v0 : SLOPE * v0;
            v1 = v1 > 0.f ? v1 : SLOPE * v1;
            split_store(OH, OL, (size_t)r * CAT + c, v0, v1);
        }
    }
}

// ---------------------------------------------------------------------------
// GCN aggregation (one warp per node), float4 gathers, writes bf16 split.
// ---------------------------------------------------------------------------
__global__ __launch_bounds__(256)
void agg_kernel(const float* __restrict__ Y, const float* __restrict__ bias,
                __nv_bfloat16* __restrict__ Oh, __nv_bfloat16* __restrict__ Ol,
                int ldc, int n)
{
    int warp = (blockIdx.x * blockDim.x + threadIdx.x) >> 5;
    int lane = threadIdx.x & 31;
    if (warp >= n) return;
    int beg = g_rowptr[warp], end = g_rowptr[warp + 1];
    int c0 = lane * 8;
    float4 a0 = make_float4(0.f, 0.f, 0.f, 0.f);
    float4 a1 = make_float4(0.f, 0.f, 0.f, 0.f);
    for (int e = beg; e < end; e++) {
        int s = g_colsrc[e];
        float w = g_dinv[s];
        const float4* yr = (const float4*)(Y + (size_t)s * EMB + c0);
        float4 y0 = yr[0], y1 = yr[1];
        a0.x += y0.x * w; a0.y += y0.y * w; a0.z += y0.z * w; a0.w += y0.w * w;
        a1.x += y1.x * w; a1.y += y1.y * w; a1.z += y1.z * w; a1.w += y1.w * w;
    }
    float di = g_dinv[warp];
    float dii = di * di;
    const float4* ys = (const float4*)(Y + (size_t)warp * EMB + c0);
    float4 s0 = ys[0], s1 = ys[1];
    const float4* bp = (const float4*)(bias + c0);
    float4 b0 = bp[0], b1 = bp[1];
    float v[8];
    v[0] = di * a0.x + dii * s0.x + b0.x;
    v[1] = di * a0.y + dii * s0.y + b0.y;
    v[2] = di * a0.z + dii * s0.z + b0.z;
    v[3] = di * a0.w + dii * s0.w + b0.w;
    v[4] = di * a1.x + dii * s1.x + b1.x;
    v[5] = di * a1.y + dii * s1.y + b1.y;
    v[6] = di * a1.z + dii * s1.z + b1.z;
    v[7] = di * a1.w + dii * s1.w + b1.w;
    size_t ob = (size_t)warp * ldc + c0;
    #pragma unroll
    for (int j = 0; j < 8; j += 2) {
        float v0 = v[j] > 0.f ? v[j] : SLOPE * v[j];
        float v1 = v[j+1] > 0.f ? v[j+1] : SLOPE * v[j+1];
        split_store(Oh, Ol, ob + j, v0, v1);
    }
}

// ---------------------------------------------------------------------------
// s_ci = sigmoid(dot + bl2), written to 3 output slots
// ---------------------------------------------------------------------------
__global__ void sci_writeout_kernel(const float* __restrict__ bl2,
                                    float* __restrict__ out, int n)
{
    int i = blockIdx.x * blockDim.x + threadIdx.x;
    if (i < n) {
        float v = 1.f / (1.f + expf(-(g_dot[i] + bl2[0])));
        out[i] = v;
        out[n + i] = v;
        out[2L * n + i] = v;
    }
}

// ---------------------------------------------------------------------------
// Launch: fork-join stream overlap (R12 structure) + fused head.
// ---------------------------------------------------------------------------
extern "C" void kernel_launch(void* const* d_in, const int* in_sizes, int n_in,
                              void* d_out, int out_size)
{
    const float* discrete_x = (const float*)d_in[0];
    const float* continous_x = (const float*)d_in[1];
    const float* Wd  = (const float*)d_in[2];
    const float* bd  = (const float*)d_in[3];
    const float* Wc1 = (const float*)d_in[4];
    const float* bc1 = (const float*)d_in[5];
    const float* Wc2 = (const float*)d_in[6];
    const float* bc2 = (const float*)d_in[7];
    const float* Wg0 = (const float*)d_in[8];
    const float* bg0 = (const float*)d_in[9];
    const float* Wg1 = (const float*)d_in[10];
    const float* bg1 = (const float*)d_in[11];
    const float* Wg2 = (const float*)d_in[12];
    const float* bg2 = (const float*)d_in[13];
    const float* Wf  = (const float*)d_in[14];
    const float* bf  = (const float*)d_in[15];
    const float* Wl1 = (const float*)d_in[16];
    const float* bl1 = (const float*)d_in[17];
    const float* Wl2 = (const float*)d_in[18];
    const float* bl2 = (const float*)d_in[19];
    const void*  edge_index = d_in[20];

    const int n = in_sizes[0] / DDISC;       // 50000
    const int e = in_sizes[20] / 2;          // 800000
    const int nblk = (n + 1023) / 1024;      // 49

    float *pY, *pB2, *pDot;
    cudaGetSymbolAddress((void**)&pY, g_Y);
    cudaGetSymbolAddress((void**)&pB2, g_b2);
    cudaGetSymbolAddress((void**)&pDot, g_dot);
    __nv_bfloat16 *pAh, *pAl, *pGh, *pGl, *pHh, *pHl, *pDh, *pDl, *pWth, *pWtl;
    cudaGetSymbolAddress((void**)&pAh, g_Ah);
    cudaGetSymbolAddress((void**)&pAl, g_Al);
    cudaGetSymbolAddress((void**)&pGh, g_Gh);
    cudaGetSymbolAddress((void**)&pGl, g_Gl);
    cudaGetSymbolAddress((void**)&pHh, g_Hh);
    cudaGetSymbolAddress((void**)&pHl, g_Hl);
    cudaGetSymbolAddress((void**)&pDh, g_Dh);
    cudaGetSymbolAddress((void**)&pDl, g_Dl);
    cudaGetSymbolAddress((void**)&pWth, g_Wth);
    cudaGetSymbolAddress((void**)&pWtl, g_Wtl);

    cudaFuncSetAttribute(mma_gemm_kernel<0,0>, cudaFuncAttributeMaxDynamicSharedMemorySize, 2*STG);
    cudaFuncSetAttribute(mma_gemm_kernel<1,2>, cudaFuncAttributeMaxDynamicSharedMemorySize, 2*STG);
    cudaFuncSetAttribute(mma_gemm_kernel<1,3>, cudaFuncAttributeMaxDynamicSharedMemorySize, 2*STG);
    cudaFuncSetAttribute(mma_gemm_kernel<1,5>, cudaFuncAttributeMaxDynamicSharedMemorySize, 2*STG);

    dim3 blk(256);
    dim3 gblk(128);
    const int mtiles = (n + 127) / 128;   // 391
    float* outf = (float*)d_out;
    long tot = (long)n * HID;
    __nv_bfloat16* nb = nullptr;
    float* nf = nullptr;

    // ---- fork: side stream for CSR prep + continuous embeds ----
    cudaStream_t s1;
    cudaStreamCreateWithFlags(&s1, cudaStreamNonBlocking);
    cudaEvent_t eFork, eJoin;
    cudaEventCreateWithFlags(&eFork, cudaEventDisableTiming);
    cudaEventCreateWithFlags(&eJoin, cudaEventDisableTiming);
    cudaEventRecord(eFork, 0);
    cudaStreamWaitEvent(s1, eFork, 0);

    // side stream: edge CSR build + dinv + dot zero + continuous embeds
    probe_kernel<<<1, 256, 0, s1>>>((const int*)edge_index, 2 * e);
    zero_cnt_kernel<<<(n + 255) / 256, blk, 0, s1>>>(n);
    count_kernel<<<(e + 255) / 256, blk, 0, s1>>>(edge_index, e, n);
    scan1_kernel<<<nblk, 1024, 0, s1>>>(n);
    scan2_kernel<<<1, 64, 0, s1>>>(nblk);
    scan3_kernel<<<nblk, 1024, 0, s1>>>(n, nblk);
    fill_kernel<<<(e + 255) / 256, blk, 0, s1>>>(edge_index, e, n);
    cont_embed_kernel<<<dim3(4, mtiles), blk, 0, s1>>>(continous_x, Wc1, bc1, Wc2, bc2,
                                                       pAh, pAl, n);

    // main stream: weight/feature splits + discrete GEMM + conv1 GEMM
    splitW_all_kernel<<<592, blk>>>(Wd, Wg0, Wg1, Wg2, Wf, Wl1, bd, bg0);
    {
        long nd = (long)n * DDISC;
        splitA_kernel<<<(unsigned)((nd + 255) / 256), blk>>>(discrete_x, pDh, pDl, nd);
    }
    mma_gemm_kernel<1,3><<<dim3(4, mtiles), gblk, 2*STG>>>(
        pDh, pDl, pWth + OW_DG, pWtl + OW_DG, pB2, nf,
        nf, nf, 0, pAh, pAl, CAT, pGh, pGl, EMB, n, DDISC, DDISC, DDISC, 512);
    mma_gemm_kernel<0,0><<<dim3(2, mtiles), gblk, 2*STG>>>(
        pGh, pGl, pWth + OW_G1, pWtl + OW_G1, nf, nf,
        pY, nf, EMB, nb, nb, 0, nb, nb, 0, n, EMB, EMB, EMB, EMB);

    // join: agg1 needs CSR (side) + conv1 GEMM (main)
    cudaEventRecord(eJoin, s1);
    cudaStreamWaitEvent(0, eJoin, 0);

    agg_kernel<<<(n * 32 + 255) / 256, blk>>>(pY, bg1, pGh, pGl, EMB, n);

    // ---- GCN conv 2 ----
    mma_gemm_kernel<0,0><<<dim3(2, mtiles), gblk, 2*STG>>>(
        pGh, pGl, pWth + OW_G2, pWtl + OW_G2, nf, nf,
        pY, nf, EMB, nb, nb, 0, nb, nb, 0, n, EMB, EMB, EMB, EMB);
    agg_kernel<<<(n * 32 + 255) / 256, blk>>>(pY, bg2, pAh + 3*EMB, pAl + 3*EMB, CAT, n);

    // ---- fusion MLP: H -> split + dual fp32 into d_out ----
    mma_gemm_kernel<1,2><<<dim3(4, mtiles), gblk, 2*STG>>>(
        pAh, pAl, pWth + OW_F, pWtl + OW_F, bf, nf,
        outf + 3L * n, outf + 3L * n + tot, HID, pHh, pHl, HID, nb, nb, 0,
        n, CAT, CAT, CAT, HID);

    // ---- Wl1 GEMM with fused head: dot(lrelu(H@Wl1+bl1), Wl2) -> g_dot ----
    mma_gemm_kernel<1,5><<<dim3(2, mtiles), gblk, 2*STG>>>(
        pHh, pHl, pWth + OW_L1, pWtl + OW_L1, bl1, Wl2,
        pDot, nf, 0, nb, nb, 0, nb, nb, 0, n, HID, HID, HID, EMB);

    // ---- s_ci = sigmoid(dot + bl2) ----
    sci_writeout_kernel<<<(n + 255) / 256, blk>>>(bl2, outf, n);

    // NOTE: s1/events intentionally not destroyed — destroying objects that
    // participated in an ongoing capture invalidates it. Host-side only.
}

// round 15
// speedup vs baseline: 1.1783x; 1.0597x over previous
#include <cuda_runtime.h>
#include <cuda_bf16.h>
#include <math.h>
#include <stdint.h>

// ---------------------------------------------------------------------------
// Problem constants
// ---------------------------------------------------------------------------
#define NN    50000
#define EE    800000
#define EMB   256
#define HID   512
#define DDISC 64
#define DCONT 13
#define CAT   (4*EMB)      // 1024
#define SLOPE 0.01f

// transposed-weight pool offsets ([N,K] row-major, bf16)
#define OW_DG  0
#define OW_G1  32768
#define OW_G2  98304
#define OW_F   163840
#define OW_L1  688128
#define OW_TOT 819200

// ---------------------------------------------------------------------------
// Scratch — __device__ globals
// ---------------------------------------------------------------------------
__device__ float g_Y [(long)NN*EMB];     // conv1 pre-aggregation
__device__ float g_Y2[(long)NN*EMB];     // conv2 pre-aggregation (separate: WAR safety)
__device__ float g_dot[NN];
__device__ float g_dinv[NN];
__device__ float g_b2[2*EMB];
__device__ int   g_cnt[NN];
__device__ int   g_rowptr[NN+1];
__device__ int   g_cursor[NN];
__device__ int   g_colsrc[EE];
__device__ int   g_blksum[64];
__device__ int   g_blkoff[64];
__device__ int   g_is64;

__device__ __align__(16) __nv_bfloat16 g_Ah[(long)NN*CAT];
__device__ __align__(16) __nv_bfloat16 g_Al[(long)NN*CAT];
__device__ __align__(16) __nv_bfloat16 g_Gh[(long)NN*EMB];
__device__ __align__(16) __nv_bfloat16 g_Gl[(long)NN*EMB];
__device__ __align__(16) __nv_bfloat16 g_Hh[(long)NN*HID];
__device__ __align__(16) __nv_bfloat16 g_Hl[(long)NN*HID];
__device__ __align__(16) __nv_bfloat16 g_Dh[(long)NN*DDISC];
__device__ __align__(16) __nv_bfloat16 g_Dl[(long)NN*DDISC];
__device__ __align__(16) __nv_bfloat16 g_Wth[OW_TOT];
__device__ __align__(16) __nv_bfloat16 g_Wtl[OW_TOT];

// ---------------------------------------------------------------------------
// asm helpers (base ISA only)
// ---------------------------------------------------------------------------
__device__ __forceinline__ uint32_t smem_u32(const void* p) {
    uint32_t a;
    asm("{ .reg .u64 t; cvta.to.shared.u64 t, %1; cvt.u32.u64 %0, t; }" : "=r"(a) : "l"(p));
    return a;
}
__device__ __forceinline__ void ldsm4(uint32_t& r0, uint32_t& r1, uint32_t& r2, uint32_t& r3,
                                      uint32_t addr) {
    asm volatile("ldmatrix.sync.aligned.m8n8.x4.shared.b16 {%0,%1,%2,%3}, [%4];"
                 : "=r"(r0), "=r"(r1), "=r"(r2), "=r"(r3) : "r"(addr));
}
__device__ __forceinline__ void mma16816(float* c, const uint32_t* a, const uint32_t* b) {
    asm volatile(
        "mma.sync.aligned.m16n8k16.row.col.f32.bf16.bf16.f32 "
        "{%0,%1,%2,%3}, {%4,%5,%6,%7}, {%8,%9}, {%0,%1,%2,%3};"
        : "+f"(c[0]), "+f"(c[1]), "+f"(c[2]), "+f"(c[3])
        : "r"(a[0]), "r"(a[1]), "r"(a[2]), "r"(a[3]), "r"(b[0]), "r"(b[1]));
}
__device__ __forceinline__ void cp16(uint32_t dst, const void* src, int sz) {
    asm volatile("cp.async.cg.shared.global [%0], [%1], 16, %2;"
                 :: "r"(dst), "l"(src), "r"(sz) : "memory");
}
__device__ __forceinline__ void cp_commit() {
    asm volatile("cp.async.commit_group;" ::: "memory");
}
__device__ __forceinline__ void cp_wait1() {
    asm volatile("cp.async.wait_group 1;" ::: "memory");
}
__device__ __forceinline__ void cp_wait0() {
    asm volatile("cp.async.wait_group 0;" ::: "memory");
}
__device__ __forceinline__ uint32_t swa(int r, int ci) {
    return (uint32_t)(r * 64 + ((ci ^ (r & 3) ^ ((r >> 2) & 1)) * 16));
}
__device__ __forceinline__ void split_store(__nv_bfloat16* H, __nv_bfloat16* L,
                                            size_t off, float v0, float v1) {
    __nv_bfloat16 h0 = __float2bfloat16(v0);
    __nv_bfloat16 h1 = __float2bfloat16(v1);
    __nv_bfloat16 l0 = __float2bfloat16(v0 - __bfloat162float(h0));
    __nv_bfloat16 l1 = __float2bfloat16(v1 - __bfloat162float(h1));
    *(__nv_bfloat162*)(H + off) = __nv_bfloat162(h0, h1);
    *(__nv_bfloat162*)(L + off) = __nv_bfloat162(l0, l1);
}

// ---------------------------------------------------------------------------
// bf16x3 HMMA GEMM, cp.async double-buffered, warp tile 64x64 (4 warps).
// MODE 0: write Cf fp32.
// MODE 2: write split (Ch,Cl) + fp32 into Cf AND Cf2.
// MODE 3: dual split dest (cols<256 vs >=256).
// MODE 5: fused head — dot(act(acc+bias), Part) per row -> atomicAdd(Cf+row).
// ---------------------------------------------------------------------------
#define STG 32768
template<int ACT, int MODE>
__global__ __launch_bounds__(128, 2)
void mma_gemm_kernel(const __nv_bfloat16* __restrict__ Ah,
                     const __nv_bfloat16* __restrict__ Al,
                     const __nv_bfloat16* __restrict__ Bh,   // [N, sB]
                     const __nv_bfloat16* __restrict__ Bl,
                     const float* __restrict__ bias,
                     const float* __restrict__ Part,
                     float* __restrict__ Cf, float* __restrict__ Cf2, int ldf,
                     __nv_bfloat16* __restrict__ Ch, __nv_bfloat16* __restrict__ Cl, int lds,
                     __nv_bfloat16* __restrict__ Ch2, __nv_bfloat16* __restrict__ Cl2, int lds2,
                     int M, int K, int sA, int sB, int N)
{
    extern __shared__ char sm[];
    const uint32_t sb = smem_u32(sm);
    const uint32_t oAH = 0, oAL = 8192, oBH = 16384, oBL = 24576;

    int tid = threadIdx.x;
    int lane = tid & 31;
    int wid = tid >> 5;
    int wm = wid & 1;
    int wn = wid >> 1;
    int row0 = blockIdx.y * 128;
    int col0 = blockIdx.x * 128;

    float acc[4][8][4];
    #pragma unroll
    for (int i = 0; i < 4; i++)
        #pragma unroll
        for (int j = 0; j < 8; j++)
            #pragma unroll
            for (int q = 0; q < 4; q++) acc[i][j][q] = 0.f;

    int Lg = lane >> 3;
    int Lr = lane & 7;
    const int nchunks = K >> 5;

    auto prefetch = [&](int ch, int stage) {
        int k0 = ch << 5;
        uint32_t base = sb + stage * STG;
        #pragma unroll
        for (int it = 0; it < 4; it++) {
            int idx = tid + it * 128;
            int r = idx >> 2, ci = idx & 3;
            uint32_t sw = swa(r, ci);
            int gr = row0 + r;
            int ok = (gr < M) ? 16 : 0;
            size_t ga = (size_t)(ok ? gr : 0) * sA + k0 + ci * 8;
            cp16(base + oAH + sw, Ah + ga, ok);
            cp16(base + oAL + sw, Al + ga, ok);
            size_t gb = (size_t)(col0 + r) * sB + k0 + ci * 8;
            cp16(base + oBH + sw, Bh + gb, 16);
            cp16(base + oBL + sw, Bl + gb, 16);
        }
        cp_commit();
    };

    prefetch(0, 0);
    for (int ch = 0; ch < nchunks; ch++) {
        if (ch + 1 < nchunks) {
            prefetch(ch + 1, (ch + 1) & 1);
            cp_wait1();
        } else {
            cp_wait0();
        }
        __syncthreads();
        uint32_t base = sb + (ch & 1) * STG;

        #pragma unroll
        for (int ks = 0; ks < 2; ks++) {
            uint32_t ah[4][4], al[4][4];
            #pragma unroll
            for (int ma = 0; ma < 4; ma++) {
                int ar = wm * 64 + ma * 16 + Lr + (Lg & 1) * 8;
                int ac = ks * 2 + (Lg >> 1);
                uint32_t sw = swa(ar, ac);
                ldsm4(ah[ma][0], ah[ma][1], ah[ma][2], ah[ma][3], base + oAH + sw);
                ldsm4(al[ma][0], al[ma][1], al[ma][2], al[ma][3], base + oAL + sw);
            }
            #pragma unroll
            for (int g = 0; g < 4; g++) {
                int br = wn * 64 + g * 16 + Lr + (Lg >> 1) * 8;
                int bc = ks * 2 + (Lg & 1);
                uint32_t sw = swa(br, bc);
                uint32_t bh[4], bl[4];
                ldsm4(bh[0], bh[1], bh[2], bh[3], base + oBH + sw);
                ldsm4(bl[0], bl[1], bl[2], bl[3], base + oBL + sw);
                #pragma unroll
                for (int ma = 0; ma < 4; ma++) {
                    mma16816(acc[ma][g*2+0], ah[ma], bh + 0);
                    mma16816(acc[ma][g*2+1], ah[ma], bh + 2);
                    mma16816(acc[ma][g*2+0], ah[ma], bl + 0);
                    mma16816(acc[ma][g*2+1], ah[ma], bl + 2);
                    mma16816(acc[ma][g*2+0], al[ma], bh + 0);
                    mma16816(acc[ma][g*2+1], al[ma], bh + 2);
                }
            }
        }
        __syncthreads();
    }

    // ---- epilogue ----
    int rbase = row0 + wm * 64 + (lane >> 2);
    int cbase = col0 + wn * 64 + (lane & 3) * 2;

    if (MODE == 5) {
        #pragma unroll
        for (int ma = 0; ma < 4; ma++) {
            #pragma unroll
            for (int h = 0; h < 2; h++) {
                int gr = rbase + ma * 16 + h * 8;
                float d = 0.f;
                #pragma unroll
                for (int na = 0; na < 8; na++) {
                    int gc = cbase + na * 8;
                    float v0 = acc[ma][na][h * 2 + 0] + bias[gc];
                    float v1 = acc[ma][na][h * 2 + 1] + bias[gc + 1];
                    v0 = v0 > 0.f ? v0 : SLOPE * v0;
                    v1 = v1 > 0.f ? v1 : SLOPE * v1;
                    d += v0 * Part[gc] + v1 * Part[gc + 1];
                }
                d += __shfl_xor_sync(0xffffffffu, d, 1);
                d += __shfl_xor_sync(0xffffffffu, d, 2);
                if ((lane & 3) == 0 && gr < M) atomicAdd(Cf + gr, d);
            }
        }
        return;
    }

    #pragma unroll
    for (int ma = 0; ma < 4; ma++) {
        #pragma unroll
        for (int na = 0; na < 8; na++) {
            int gc = cbase + na * 8;
            float b0 = bias ? bias[gc] : 0.f;
            float b1 = bias ? bias[gc + 1] : 0.f;
            #pragma unroll
            for (int h = 0; h < 2; h++) {
                int gr = rbase + ma * 16 + h * 8;
                if (gr < M) {
                    float v0 = acc[ma][na][h * 2 + 0] + b0;
                    float v1 = acc[ma][na][h * 2 + 1] + b1;
                    if (ACT == 1) {
                        v0 = v0 > 0.f ? v0 : SLOPE * v0;
                        v1 = v1 > 0.f ? v1 : SLOPE * v1;
                    }
                    if (MODE == 0 || MODE == 2) {
                        *(float2*)(Cf + (size_t)gr * ldf + gc) = make_float2(v0, v1);
                        if (MODE == 2)
                            *(float2*)(Cf2 + (size_t)gr * ldf + gc) = make_float2(v0, v1);
                    }
                    if (MODE == 2)
                        split_store(Ch, Cl, (size_t)gr * lds + gc, v0, v1);
                    if (MODE == 3) {
                        if (gc < 256)
                            split_store(Ch, Cl, (size_t)gr * lds + gc, v0, v1);
                        else
                            split_store(Ch2, Cl2, (size_t)gr * lds2 + (gc - 256), v0, v1);
                    }
                }
            }
        }
    }
}

// ---------------------------------------------------------------------------
// splits / prep (unchanged from R14)
// ---------------------------------------------------------------------------
__global__ void splitA_kernel(const float* __restrict__ X,
                              __nv_bfloat16* __restrict__ H,
                              __nv_bfloat16* __restrict__ L, long n)
{
    long i = (long)blockIdx.x * blockDim.x + threadIdx.x;
    if (i >= n) return;
    float a = X[i];
    __nv_bfloat16 h = __float2bfloat16(a);
    H[i] = h;
    L[i] = __float2bfloat16(a - __bfloat162float(h));
}

__global__ void splitW_all_kernel(const float* __restrict__ Wd,  const float* __restrict__ Wg0,
                                  const float* __restrict__ Wg1, const float* __restrict__ Wg2,
                                  const float* __restrict__ Wf,  const float* __restrict__ Wl1,
                                  const float* __restrict__ bd,  const float* __restrict__ bg0)
{
    const int c0 = DDISC*EMB;
    const int c1 = c0 + DDISC*EMB;
    const int c2 = c1 + EMB*EMB;
    const int c3 = c2 + EMB*EMB;
    const int c4 = c3 + CAT*HID;
    const int c5 = c4 + HID*EMB;
    for (long i = (long)blockIdx.x * blockDim.x + threadIdx.x;
         i < c5 + 2*EMB; i += (long)gridDim.x * blockDim.x) {
        if (i >= c5) {
            int j = (int)(i - c5);
            g_b2[j] = (j < EMB) ? bd[j] : bg0[j - EMB];
            continue;
        }
        const float* W; long loc, off; int K, N;
        if (i < c0)      { W = Wd;  loc = i;      off = OW_DG;           K = DDISC; N = EMB; }
        else if (i < c1) { W = Wg0; loc = i - c0; off = OW_DG + (long)EMB*DDISC; K = DDISC; N = EMB; }
        else if (i < c2) { W = Wg1; loc = i - c1; off = OW_G1; K = EMB; N = EMB; }
        else if (i < c3) { W = Wg2; loc = i - c2; off = OW_G2; K = EMB; N = EMB; }
        else if (i < c4) { W = Wf;  loc = i - c3; off = OW_F;  K = CAT; N = HID; }
        else             { W = Wl1; loc = i - c4; off = OW_L1; K = HID; N = EMB; }
        int k = (int)(loc / N), nn = (int)(loc % N);
        float a = W[loc];
        __nv_bfloat16 h = __float2bfloat16(a);
        long o = off + (long)nn * K + k;
        g_Wth[o] = h;
        g_Wtl[o] = __float2bfloat16(a - __bfloat162float(h));
    }
}

__global__ void probe_kernel(const int* __restrict__ ei32, int nwords)
{
    __shared__ int nz;
    if (threadIdx.x == 0) nz = 0;
    __syncthreads();
    int lim = nwords < 4096 ? nwords : 4096;
    for (int i = 1 + 2 * threadIdx.x; i < lim; i += 2 * blockDim.x)
        if (ei32[i] != 0) atomicAdd(&nz, 1);
    __syncthreads();
    if (threadIdx.x == 0) g_is64 = (nz == 0) ? 1 : 0;
}

__device__ __forceinline__ int edge_at(const void* base, long i, int is64)
{
    return is64 ? (int)((const long long*)base)[i] : ((const int*)base)[i];
}

__global__ void zero_cnt_kernel(int n) {
    int i = blockIdx.x * blockDim.x + threadIdx.x;
    if (i < n) {
        g_cnt[i] = 0;
        g_dot[i] = 0.f;
    }
}

__global__ void count_kernel(const void* __restrict__ ei, int e, int n) {
    int i = blockIdx.x * blockDim.x + threadIdx.x;
    if (i >= e) return;
    int is64 = g_is64;
    int d = edge_at(ei, (long)e + i, is64);
    if ((unsigned)d < (unsigned)n) atomicAdd(&g_cnt[d], 1);
}

__global__ __launch_bounds__(1024)
void scan1_kernel(int n) {
    __shared__ int sh[1024];
    int i = blockIdx.x * 1024 + threadIdx.x;
    int v = (i < n) ? g_cnt[i] : 0;
    if (i < n) g_dinv[i] = rsqrtf((float)(v + 1));
    sh[threadIdx.x] = v;
    __syncthreads();
    #pragma unroll
    for (int off = 512; off > 0; off >>= 1) {
        if (threadIdx.x < off) sh[threadIdx.x] += sh[threadIdx.x + off];
        __syncthreads();
    }
    if (threadIdx.x == 0) g_blksum[blockIdx.x] = sh[0];
}

__global__ void scan2_kernel(int nblk) {
    __shared__ int sh[64];
    int t = threadIdx.x;
    int v = (t < nblk) ? g_blksum[t] : 0;
    sh[t] = v;
    __syncthreads();
    #pragma unroll
    for (int off = 1; off < 64; off <<= 1) {
        int u = (t >= off) ? sh[t - off] : 0;
        __syncthreads();
        sh[t] += u;
        __syncthreads();
    }
    if (t < nblk) g_blkoff[t] = sh[t] - v;
}

__global__ __launch_bounds__(1024)
void scan3_kernel(int n, int nblk) {
    __shared__ int sh[1024];
    int i = blockIdx.x * 1024 + threadIdx.x;
    int v = (i < n) ? g_cnt[i] : 0;
    sh[threadIdx.x] = v;
    __syncthreads();
    #pragma unroll
    for (int off = 1; off < 1024; off <<= 1) {
        int u = (threadIdx.x >= off) ? sh[threadIdx.x - off] : 0;
        __syncthreads();
        sh[threadIdx.x] += u;
        __syncthreads();
    }
    int off0 = g_blkoff[blockIdx.x];
    if (i < n) {
        int ex = off0 + sh[threadIdx.x] - v;
        g_rowptr[i] = ex;
        g_cursor[i] = ex;
    }
    if (blockIdx.x == nblk - 1 && threadIdx.x == 1023)
        g_rowptr[n] = off0 + sh[1023];
}

__global__ void fill_kernel(const void* __restrict__ ei, int e, int n) {
    int i = blockIdx.x * blockDim.x + threadIdx.x;
    if (i >= e) return;
    int is64 = g_is64;
    int s = edge_at(ei, i, is64);
    int d = edge_at(ei, (long)e + i, is64);
    if ((unsigned)d < (unsigned)n && (unsigned)s < (unsigned)n) {
        int pos = atomicAdd(&g_cursor[d], 1);
        if (pos < EE) g_colsrc[pos] = s;
    }
}

__global__ __launch_bounds__(256)
void cont_embed_kernel(const float* __restrict__ X,
                       const float* __restrict__ Wc1, const float* __restrict__ bc1,
                       const float* __restrict__ Wc2, const float* __restrict__ bc2,
                       __nv_bfloat16* __restrict__ Ch, __nv_bfloat16* __restrict__ Cl,
                       int M)
{
    const int K = DCONT, NC = EMB, lda = 3*DCONT;
    int half = blockIdx.x >> 1;
    int col0 = (blockIdx.x & 1) * 128;
    const float* A = X + half * DCONT;
    const float* W = half ? Wc2 : Wc1;
    const float* bias = half ? bc2 : bc1;
    __nv_bfloat16* OH = Ch + (1 + half) * EMB;
    __nv_bfloat16* OL = Cl + (1 + half) * EMB;

    __shared__ float As[16][128];
    __shared__ float Ws[16][128];

    int tid = threadIdx.x;
    int tx = tid & 15;
    int ty = tid >> 4;
    int row0 = blockIdx.y * 128;

    float acc[8][8];
    #pragma unroll
    for (int i = 0; i < 8; i++)
        #pragma unroll
        for (int j = 0; j < 8; j++) acc[i][j] = 0.f;

    {
        int a_row = tid >> 1;
        int a_col = (tid & 1) * 8;
        #pragma unroll
        for (int j = 0; j < 8; j++) {
            int r = row0 + a_row, c = a_col + j;
            As[a_col + j][a_row] = (r < M && c < K) ? A[(long)r * lda + c] : 0.f;
        }
        int w_k = tid >> 5;
        int w_n = (tid & 31) * 4;
        #pragma unroll
        for (int rep = 0; rep < 2; rep++) {
            int kk = w_k + rep * 8;
            #pragma unroll
            for (int j = 0; j < 4; j++) {
                int nn = col0 + w_n + j;
                Ws[kk][w_n + j] = (kk < K) ? W[(long)kk * NC + nn] : 0.f;
            }
        }
    }
    __syncthreads();
    #pragma unroll
    for (int k = 0; k < 13; k++) {
        float a[8], b[8];
        #pragma unroll
        for (int i = 0; i < 8; i++) a[i] = As[k][ty * 8 + i];
        #pragma unroll
        for (int j = 0; j < 8; j++) b[j] = Ws[k][tx * 8 + j];
        #pragma unroll
        for (int i = 0; i < 8; i++)
            #pragma unroll
            for (int j = 0; j < 8; j++)
                acc[i][j] += a[i] * b[j];
    }

    #pragma unroll
    for (int i = 0; i < 8; i++) {
        int r = row0 + ty * 8 + i;
        if (r >= M) continue;
        #pragma unroll
        for (int j = 0; j < 8; j += 2) {
            int c = col0 + tx * 8 + j;
            float v0 = acc[i][j] + bias[c];
            float v1 = acc[i][j + 1] + bias[c + 1];
            v0 = v0 > 0.f ? v0 : SLOPE * v0;
            v1 = v1 > 0.f ? v1 : SLOPE * v1;
            split_store(OH, OL, (size_t)r * CAT + c, v0, v1);
        }
    }
}

// ---------------------------------------------------------------------------
// GCN aggregation over node range [n0, n0+cnt)
// ---------------------------------------------------------------------------
__global__ __launch_bounds__(256)
void agg_kernel(const float* __restrict__ Y, const float* __restrict__ bias,
                __nv_bfloat16* __restrict__ Oh, __nv_bfloat16* __restrict__ Ol,
                int ldc, int n0, int cnt)
{
    int w = (blockIdx.x * blockDim.x + threadIdx.x) >> 5;
    int lane = threadIdx.x & 31;
    if (w >= cnt) return;
    int warp = n0 + w;
    int beg = g_rowptr[warp], end = g_rowptr[warp + 1];
    int c0 = lane * 8;
    float4 a0 = make_float4(0.f, 0.f, 0.f, 0.f);
    float4 a1 = make_float4(0.f, 0.f, 0.f, 0.f);
    for (int e = beg; e < end; e++) {
        int s = g_colsrc[e];
        float w2 = g_dinv[s];
        const float4* yr = (const float4*)(Y + (size_t)s * EMB + c0);
        float4 y0 = yr[0], y1 = yr[1];
        a0.x += y0.x * w2; a0.y += y0.y * w2; a0.z += y0.z * w2; a0.w += y0.w * w2;
        a1.x += y1.x * w2; a1.y += y1.y * w2; a1.z += y1.z * w2; a1.w += y1.w * w2;
    }
    float di = g_dinv[warp];
    float dii = di * di;
    const float4* ys = (const float4*)(Y + (size_t)warp * EMB + c0);
    float4 s0 = ys[0], s1 = ys[1];
    const float4* bp = (const float4*)(bias + c0);
    float4 b0 = bp[0], b1 = bp[1];
    float v[8];
    v[0] = di * a0.x + dii * s0.x + b0.x;
    v[1] = di * a0.y + dii * s0.y + b0.y;
    v[2] = di * a0.z + dii * s0.z + b0.z;
    v[3] = di * a0.w + dii * s0.w + b0.w;
    v[4] = di * a1.x + dii * s1.x + b1.x;
    v[5] = di * a1.y + dii * s1.y + b1.y;
    v[6] = di * a1.z + dii * s1.z + b1.z;
    v[7] = di * a1.w + dii * s1.w + b1.w;
    size_t ob = (size_t)warp * ldc + c0;
    #pragma unroll
    for (int j = 0; j < 8; j += 2) {
        float v0 = v[j] > 0.f ? v[j] : SLOPE * v[j];
        float v1 = v[j+1] > 0.f ? v[j+1] : SLOPE * v[j+1];
        split_store(Oh, Ol, ob + j, v0, v1);
    }
}

__global__ void sci_writeout_kernel(const float* __restrict__ bl2,
                                    float* __restrict__ out, int n)
{
    int i = blockIdx.x * blockDim.x + threadIdx.x;
    if (i < n) {
        float v = 1.f / (1.f + expf(-(g_dot[i] + bl2[0])));
        out[i] = v;
        out[n + i] = v;
        out[2L * n + i] = v;
    }
}

// ---------------------------------------------------------------------------
// Launch: fork-join + row-chunk pipelined tail (tensor ∥ L2 overlap).
// ---------------------------------------------------------------------------
extern "C" void kernel_launch(void* const* d_in, const int* in_sizes, int n_in,
                              void* d_out, int out_size)
{
    const float* discrete_x = (const float*)d_in[0];
    const float* continous_x = (const float*)d_in[1];
    const float* Wd  = (const float*)d_in[2];
    const float* bd  = (const float*)d_in[3];
    const float* Wc1 = (const float*)d_in[4];
    const float* bc1 = (const float*)d_in[5];
    const float* Wc2 = (const float*)d_in[6];
    const float* bc2 = (const float*)d_in[7];
    const float* Wg0 = (const float*)d_in[8];
    const float* bg0 = (const float*)d_in[9];
    const float* Wg1 = (const float*)d_in[10];
    const float* bg1 = (const float*)d_in[11];
    const float* Wg2 = (const float*)d_in[12];
    const float* bg2 = (const float*)d_in[13];
    const float* Wf  = (const float*)d_in[14];
    const float* bf  = (const float*)d_in[15];
    const float* Wl1 = (const float*)d_in[16];
    const float* bl1 = (const float*)d_in[17];
    const float* Wl2 = (const float*)d_in[18];
    const float* bl2 = (const float*)d_in[19];
    const void*  edge_index = d_in[20];

    const int n = in_sizes[0] / DDISC;       // 50000
    const int e = in_sizes[20] / 2;          // 800000
    const int nblk = (n + 1023) / 1024;      // 49

    // row chunks
    const int m0 = 25088;                    // 196 tiles
    const int m1 = n - m0;                   // 24912
    const int t0 = 196, t1 = (m1 + 127) / 128;   // 195

    float *pY, *pY2, *pB2, *pDot;
    cudaGetSymbolAddress((void**)&pY,  g_Y);
    cudaGetSymbolAddress((void**)&pY2, g_Y2);
    cudaGetSymbolAddress((void**)&pB2, g_b2);
    cudaGetSymbolAddress((void**)&pDot, g_dot);
    __nv_bfloat16 *pAh, *pAl, *pGh, *pGl, *pHh, *pHl, *pDh, *pDl, *pWth, *pWtl;
    cudaGetSymbolAddress((void**)&pAh, g_Ah);
    cudaGetSymbolAddress((void**)&pAl, g_Al);
    cudaGetSymbolAddress((void**)&pGh, g_Gh);
    cudaGetSymbolAddress((void**)&pGl, g_Gl);
    cudaGetSymbolAddress((void**)&pHh, g_Hh);
    cudaGetSymbolAddress((void**)&pHl, g_Hl);
    cudaGetSymbolAddress((void**)&pDh, g_Dh);
    cudaGetSymbolAddress((void**)&pDl, g_Dl);
    cudaGetSymbolAddress((void**)&pWth, g_Wth);
    cudaGetSymbolAddress((void**)&pWtl, g_Wtl);

    cudaFuncSetAttribute(mma_gemm_kernel<0,0>, cudaFuncAttributeMaxDynamicSharedMemorySize, 2*STG);
    cudaFuncSetAttribute(mma_gemm_kernel<1,2>, cudaFuncAttributeMaxDynamicSharedMemorySize, 2*STG);
    cudaFuncSetAttribute(mma_gemm_kernel<1,3>, cudaFuncAttributeMaxDynamicSharedMemorySize, 2*STG);
    cudaFuncSetAttribute(mma_gemm_kernel<1,5>, cudaFuncAttributeMaxDynamicSharedMemorySize, 2*STG);

    dim3 blk(256);
    dim3 gblk(128);
    const int mtiles = (n + 127) / 128;
    float* outf = (float*)d_out;
    long tot = (long)n * HID;
    __nv_bfloat16* nb = nullptr;
    float* nf = nullptr;

    cudaStream_t s1;
    cudaStreamCreateWithFlags(&s1, cudaStreamNonBlocking);
    cudaEvent_t eFork, eCSR, eEmb, eC1, eM0, eS0, eS1;
    cudaEventCreateWithFlags(&eFork, cudaEventDisableTiming);
    cudaEventCreateWithFlags(&eCSR,  cudaEventDisableTiming);
    cudaEventCreateWithFlags(&eEmb,  cudaEventDisableTiming);
    cudaEventCreateWithFlags(&eC1,   cudaEventDisableTiming);
    cudaEventCreateWithFlags(&eM0,   cudaEventDisableTiming);
    cudaEventCreateWithFlags(&eS0,   cudaEventDisableTiming);
    cudaEventCreateWithFlags(&eS1,   cudaEventDisableTiming);
    cudaEventRecord(eFork, 0);
    cudaStreamWaitEvent(s1, eFork, 0);

    // ---- s1: CSR build (+dot zero) + cont embeds ----
    probe_kernel<<<1, 256, 0, s1>>>((const int*)edge_index, 2 * e);
    zero_cnt_kernel<<<(n + 255) / 256, blk, 0, s1>>>(n);
    count_kernel<<<(e + 255) / 256, blk, 0, s1>>>(edge_index, e, n);
    scan1_kernel<<<nblk, 1024, 0, s1>>>(n);
    scan2_kernel<<<1, 64, 0, s1>>>(nblk);
    scan3_kernel<<<nblk, 1024, 0, s1>>>(n, nblk);
    fill_kernel<<<(e + 255) / 256, blk, 0, s1>>>(edge_index, e, n);
    cudaEventRecord(eCSR, s1);
    cont_embed_kernel<<<dim3(4, mtiles), blk, 0, s1>>>(continous_x, Wc1, bc1, Wc2, bc2,
                                                       pAh, pAl, n);
    cudaEventRecord(eEmb, s1);

    // ---- main: splits + discrete GEMM + conv1 GEMM (full) ----
    splitW_all_kernel<<<592, blk>>>(Wd, Wg0, Wg1, Wg2, Wf, Wl1, bd, bg0);
    {
        long nd = (long)n * DDISC;
        splitA_kernel<<<(unsigned)((nd + 255) / 256), blk>>>(discrete_x, pDh, pDl, nd);
    }
    mma_gemm_kernel<1,3><<<dim3(4, mtiles), gblk, 2*STG>>>(
        pDh, pDl, pWth + OW_DG, pWtl + OW_DG, pB2, nf,
        nf, nf, 0, pAh, pAl, CAT, pGh, pGl, EMB, n, DDISC, DDISC, DDISC, 512);
    mma_gemm_kernel<0,0><<<dim3(2, mtiles), gblk, 2*STG>>>(
        pGh, pGl, pWth + OW_G1, pWtl + OW_G1, nf, nf,
        pY, nf, EMB, nb, nb, 0, nb, nb, 0, n, EMB, EMB, EMB, EMB);
    cudaEventRecord(eC1, 0);

    // ---- chunked pipeline: agg1 / conv2 ----
    // main: chunk 0
    cudaStreamWaitEvent(0, eCSR, 0);
    agg_kernel<<<(m0 * 32 + 255) / 256, blk>>>(pY, bg1, pGh, pGl, EMB, 0, m0);
    mma_gemm_kernel<0,0><<<dim3(2, t0), gblk, 2*STG>>>(
        pGh, pGl, pWth + OW_G2, pWtl + OW_G2, nf, nf,
        pY2, nf, EMB, nb, nb, 0, nb, nb, 0, m0, EMB, EMB, EMB, EMB);
    cudaEventRecord(eM0, 0);
    // s1: chunk 1 (needs conv1 from main; CSR is local)
    cudaStreamWaitEvent(s1, eC1, 0);
    agg_kernel<<<(m1 * 32 + 255) / 256, blk, 0, s1>>>(pY, bg1, pGh, pGl, EMB, m0, m1);
    mma_gemm_kernel<0,0><<<dim3(2, t1), gblk, 2*STG, s1>>>(
        pGh + (size_t)m0 * EMB, pGl + (size_t)m0 * EMB,
        pWth + OW_G2, pWtl + OW_G2, nf, nf,
        pY2 + (size_t)m0 * EMB, nf, EMB, nb, nb, 0, nb, nb, 0, m1, EMB, EMB, EMB, EMB);
    cudaEventRecord(eS0, s1);

    // ---- chunked tail: agg2 -> fusion -> Wl1+head ----
    // main chunk 0 (agg2 needs BOTH conv2 halves)
    cudaStreamWaitEvent(0, eS0, 0);
    agg_kernel<<<(m0 * 32 + 255) / 256, blk>>>(pY2, bg2, pAh + 3*EMB, pAl + 3*EMB, CAT, 0, m0);
    cudaStreamWaitEvent(0, eEmb, 0);
    mma_gemm_kernel<1,2><<<dim3(4, t0), gblk, 2*STG>>>(
        pAh, pAl, pWth + OW_F, pWtl + OW_F, bf, nf,
        outf + 3L * n, outf + 3L * n + tot, HID, pHh, pHl, HID, nb, nb, 0,
        m0, CAT, CAT, CAT, HID);
    mma_gemm_kernel<1,5><<<dim3(2, t0), gblk, 2*STG>>>(
        pHh, pHl, pWth + OW_L1, pWtl + OW_L1, bl1, Wl2,
        pDot, nf, 0, nb, nb, 0, nb, nb, 0, m0, HID, HID, HID, EMB);
    // s1 chunk 1 (conv2_c0 done via eM0; conv2_c1 local)
    cudaStreamWaitEvent(s1, eM0, 0);
    agg_kernel<<<(m1 * 32 + 255) / 256, blk, 0, s1>>>(pY2, bg2, pAh + 3*EMB, pAl + 3*EMB, CAT, m0, m1);
    mma_gemm_kernel<1,2><<<dim3(4, t1), gblk, 2*STG, s1>>>(
        pAh + (size_t)m0 * CAT, pAl + (size_t)m0 * CAT,
        pWth + OW_F, pWtl + OW_F, bf, nf,
        outf + 3L * n + (size_t)m0 * HID, outf + 3L * n + tot + (size_t)m0 * HID, HID,
        pHh + (size_t)m0 * HID, pHl + (size_t)m0 * HID, HID, nb, nb, 0,
        m1, CAT, CAT, CAT, HID);
    mma_gemm_kernel<1,5><<<dim3(2, t1), gblk, 2*STG, s1>>>(
        pHh + (size_t)m0 * HID, pHl + (size_t)m0 * HID,
        pWth + OW_L1, pWtl + OW_L1, bl1, Wl2,
        pDot + m0, nf, 0, nb, nb, 0, nb, nb, 0, m1, HID, HID, HID, EMB);
    cudaEventRecord(eS1, s1);

    // ---- s_ci writeout (needs both head chunks) ----
    cudaStreamWaitEvent(0, eS1, 0);
    sci_writeout_kernel<<<(n + 255) / 256, blk>>>(bl2, outf, n);

    // NOTE: s1/events intentionally not destroyed — destroying objects that
    // participated in an ongoing capture invalidates it. Host-side only.
}